// round 10
// baseline (speedup 1.0000x reference)
#include <cuda_runtime.h>
#include <cuda_bf16.h>
#include <cuda_fp16.h>
#include <cstdint>

#define B_  8
#define S_  1024
#define NX_ 1024
#define H_  16
#define D_  64

// ---------------- scratch (__device__ globals; no allocation) ----------------
__device__ __half g_xhi[B_ * S_ * NX_];
__device__ __half g_xlo[B_ * S_ * NX_];
__device__ __half g_ahi[B_ * S_ * NX_];              // attention out, fp16 hi
__device__ __half g_alo[B_ * S_ * NX_];              // attention out, fp16 lo
__device__ __half g_wqkv_h[3 * NX_ * NX_];           // [N=3072, K=1024] fp16 trunc
__device__ __half g_wproj_h[NX_ * NX_];              // [N=1024, K=1024]
// attention operands, written by QKV GEMM epilogue: bf16 hi/lo, [b,h,s,d]
__device__ __nv_bfloat16 g_qhi[B_ * H_ * S_ * D_];   // pre-scaled by 0.125
__device__ __nv_bfloat16 g_qlo[B_ * H_ * S_ * D_];
__device__ __nv_bfloat16 g_khi[B_ * H_ * S_ * D_];
__device__ __nv_bfloat16 g_klo[B_ * H_ * S_ * D_];
__device__ __nv_bfloat16 g_vhi[B_ * H_ * S_ * D_];
__device__ __nv_bfloat16 g_vlo[B_ * H_ * S_ * D_];

// ---------------- PTX helpers ----------------
__device__ __forceinline__ uint32_t smem_to_u32(const void* p) {
    uint32_t a;
    asm("{ .reg .u64 t; cvta.to.shared.u64 t, %1; cvt.u32.u64 %0, t; }"
        : "=r"(a) : "l"(p));
    return a;
}
__device__ __forceinline__ void cp_async16(uint32_t dst, const void* src) {
    asm volatile("cp.async.cg.shared.global [%0], [%1], 16;"
                 :: "r"(dst), "l"(src) : "memory");
}
#define CP_COMMIT() asm volatile("cp.async.commit_group;" ::: "memory")
#define CP_WAIT(n)  asm volatile("cp.async.wait_group %0;" :: "n"(n) : "memory")

__device__ __forceinline__ void ldsm_x4(uint32_t& r0, uint32_t& r1,
                                        uint32_t& r2, uint32_t& r3, uint32_t addr) {
    asm volatile("ldmatrix.sync.aligned.m8n8.x4.shared.b16 {%0,%1,%2,%3}, [%4];"
                 : "=r"(r0), "=r"(r1), "=r"(r2), "=r"(r3) : "r"(addr));
}
__device__ __forceinline__ void ldsm_x4t(uint32_t& r0, uint32_t& r1,
                                         uint32_t& r2, uint32_t& r3, uint32_t addr) {
    asm volatile("ldmatrix.sync.aligned.m8n8.x4.trans.shared.b16 {%0,%1,%2,%3}, [%4];"
                 : "=r"(r0), "=r"(r1), "=r"(r2), "=r"(r3) : "r"(addr));
}
// bf16 MMA (attention)
__device__ __forceinline__ void mma16816(float* c, const uint32_t* a, const uint32_t* b) {
    asm volatile("mma.sync.aligned.m16n8k16.row.col.f32.bf16.bf16.f32 "
                 "{%0,%1,%2,%3}, {%4,%5,%6,%7}, {%8,%9}, {%0,%1,%2,%3};"
                 : "+f"(c[0]), "+f"(c[1]), "+f"(c[2]), "+f"(c[3])
                 : "r"(a[0]), "r"(a[1]), "r"(a[2]), "r"(a[3]),
                   "r"(b[0]), "r"(b[1]));
}
// fp16 MMA (GEMMs)
__device__ __forceinline__ void mma16816h(float* c, const uint32_t* a, const uint32_t* b) {
    asm volatile("mma.sync.aligned.m16n8k16.row.col.f32.f16.f16.f32 "
                 "{%0,%1,%2,%3}, {%4,%5,%6,%7}, {%8,%9}, {%0,%1,%2,%3};"
                 : "+f"(c[0]), "+f"(c[1]), "+f"(c[2]), "+f"(c[3])
                 : "r"(a[0]), "r"(a[1]), "r"(a[2]), "r"(a[3]),
                   "r"(b[0]), "r"(b[1]));
}
__device__ __forceinline__ void split32(float v, __nv_bfloat16& h, __nv_bfloat16& l) {
    h = __float2bfloat16(v);
    l = __float2bfloat16(v - __bfloat162float(h));
}
__device__ __forceinline__ void split16(float v, __half& h, __half& l) {
    h = __float2half(v);
    l = __float2half(v - __half2float(h));
}

// ---------------------------------------------------------------------------
// split: fp32 -> (hi, lo) fp16, same layout (input x only).
// ---------------------------------------------------------------------------
__global__ void split_kernel(const float* __restrict__ in,
                             __half* __restrict__ hi,
                             __half* __restrict__ lo, int n4)
{
    int i = blockIdx.x * blockDim.x + threadIdx.x;
    if (i >= n4) return;
    float4 v = ((const float4*)in)[i];
    __half h0, h1, h2, h3, l0, l1, l2, l3;
    split16(v.x, h0, l0); split16(v.y, h1, l1);
    split16(v.z, h2, l2); split16(v.w, h3, l3);
    ((__half2*)hi)[2 * i]     = __half2(h0, h1);
    ((__half2*)hi)[2 * i + 1] = __half2(h2, h3);
    ((__half2*)lo)[2 * i]     = __half2(l0, l1);
    ((__half2*)lo)[2 * i + 1] = __half2(l2, l3);
}

// ---------------------------------------------------------------------------
// transpose + truncate: W[K,N] fp32 -> T_h [N,K] fp16
// ---------------------------------------------------------------------------
__global__ void tsplit_kernel(const float* __restrict__ W,
                              __half* __restrict__ Th, int K, int N)
{
    __shared__ float t[32][33];
    int n0 = blockIdx.x * 32, k0 = blockIdx.y * 32;
    int tx = threadIdx.x, ty = threadIdx.y;  // 32 x 8
#pragma unroll
    for (int i = 0; i < 4; i++)
        t[ty + i * 8][tx] = W[(long)(k0 + ty + i * 8) * N + n0 + tx];
    __syncthreads();
#pragma unroll
    for (int i = 0; i < 4; i++) {
        float v = t[tx][ty + i * 8];
        Th[(long)(n0 + ty + i * 8) * K + k0 + tx] = __float2half(v);
    }
}

// ---------------------------------------------------------------------------
// Shared GEMM mainloop: fp16 2-product, 128x128x32 CTA tile, 128 threads,
// 4 warps (2Mx2N), 64x64 warp tile, 3-stage cp.async pipeline.
// ---------------------------------------------------------------------------
#define ROWB    80
#define TILE_B  (128 * ROWB)
#define STAGE_B (3 * TILE_B)
#define NSTAGE  3
#define GEMM_SMEM_DYN (NSTAGE * STAGE_B)

#define GEMM_MAINLOOP(Ahi, Alo, Bh, K)                                          \
    extern __shared__ __align__(128) char smem[];                               \
    const uint32_t sbase = smem_to_u32(smem);                                   \
    const int tid  = threadIdx.x;                                               \
    const int lane = tid & 31;                                                  \
    const int wid  = tid >> 5;                                                  \
    const int wm   = wid & 1;                                                   \
    const int wn   = wid >> 1;                                                  \
    const int bm   = blockIdx.y * 128;                                          \
    const int bn   = blockIdx.x * 128;                                          \
    float acc[4][8][4];                                                         \
    _Pragma("unroll")                                                           \
    for (int mi = 0; mi < 4; mi++)                                              \
        _Pragma("unroll")                                                       \
        for (int ni = 0; ni < 8; ni++)                                          \
            _Pragma("unroll")                                                   \
            for (int r = 0; r < 4; r++) acc[mi][ni][r] = 0.f;                   \
    const __half* gA[2] = { Ahi + (long)bm * (K), Alo + (long)bm * (K) };       \
    const __half* gB = Bh + (long)bn * (K);                                     \
    const int NS = (K) / 32;                                                    \
    auto load_stage = [&](int s) {                                              \
        const int k0 = s * 32;                                                  \
        const uint32_t buf = sbase + (s % NSTAGE) * STAGE_B;                    \
        _Pragma("unroll")                                                       \
        for (int c = 0; c < 4; c++) {                                           \
            _Pragma("unroll")                                                   \
            for (int t = 0; t < 2; t++)                                         \
                cp_async16(buf + t * TILE_B + tid * ROWB + c * 16,              \
                           gA[t] + (long)tid * (K) + k0 + c * 8);               \
            cp_async16(buf + 2 * TILE_B + tid * ROWB + c * 16,                  \
                       gB + (long)tid * (K) + k0 + c * 8);                      \
        }                                                                       \
    };                                                                          \
    load_stage(0);                                                              \
    CP_COMMIT();                                                                \
    load_stage(1);                                                              \
    CP_COMMIT();                                                                \
    const int arow  = wm * 64 + (lane & 15);                                    \
    const int asel  = (lane >> 4) << 3;                                         \
    const int brow  = wn * 64 + (lane & 7) + ((lane >> 4) << 3);                \
    const int bsel  = ((lane >> 3) & 1) << 3;                                   \
    for (int s = 0; s < NS; s++) {                                              \
        if (s + 2 < NS) {                                                       \
            load_stage(s + 2);                                                  \
            CP_COMMIT();                                                        \
            CP_WAIT(2);                                                         \
        } else {                                                                \
            CP_WAIT(0);                                                         \
        }                                                                       \
        __syncthreads();                                                        \
        const uint32_t buf = sbase + (s % NSTAGE) * STAGE_B;                    \
        _Pragma("unroll")                                                       \
        for (int ks = 0; ks < 2; ks++) {                                        \
            uint32_t a[4][4];                                                   \
            uint32_t b[8][2];                                                   \
            const int acol = ks * 16 + asel;                                    \
            const int bcol = ks * 16 + bsel;                                    \
            _Pragma("unroll")                                                   \
            for (int nj = 0; nj < 4; nj++)                                      \
                ldsm_x4(b[nj * 2][0], b[nj * 2][1],                             \
                        b[nj * 2 + 1][0], b[nj * 2 + 1][1],                     \
                        buf + 2 * TILE_B + (brow + nj * 16) * ROWB + bcol * 2); \
            _Pragma("unroll")                                                   \
            for (int mi = 0; mi < 4; mi++)                                      \
                ldsm_x4(a[mi][0], a[mi][1], a[mi][2], a[mi][3],                 \
                        buf + 0 * TILE_B + (arow + mi * 16) * ROWB + acol * 2); \
            _Pragma("unroll")                                                   \
            for (int mi = 0; mi < 4; mi++)                                      \
                _Pragma("unroll")                                               \
                for (int ni = 0; ni < 8; ni++)                                  \
                    mma16816h(acc[mi][ni], a[mi], b[ni]);                       \
            _Pragma("unroll")                                                   \
            for (int mi = 0; mi < 4; mi++)                                      \
                ldsm_x4(a[mi][0], a[mi][1], a[mi][2], a[mi][3],                 \
                        buf + 1 * TILE_B + (arow + mi * 16) * ROWB + acol * 2); \
            _Pragma("unroll")                                                   \
            for (int mi = 0; mi < 4; mi++)                                      \
                _Pragma("unroll")                                               \
                for (int ni = 0; ni < 8; ni++)                                  \
                    mma16816h(acc[mi][ni], a[mi], b[ni]);                       \
        }                                                                       \
        __syncthreads();                                                        \
    }

// ---------------------------------------------------------------------------
// Projection GEMM: fp32 out + bias (final output)
// ---------------------------------------------------------------------------
__global__ void __launch_bounds__(128, 2) gemm_proj(
    const __half* __restrict__ Ahi, const __half* __restrict__ Alo,
    const __half* __restrict__ Bh,
    const float* __restrict__ bias, float* __restrict__ C, int N, int K)
{
    GEMM_MAINLOOP(Ahi, Alo, Bh, K)

    const int g  = lane >> 2;
    const int t4 = lane & 3;
#pragma unroll
    for (int mi = 0; mi < 4; mi++) {
#pragma unroll
        for (int ni = 0; ni < 8; ni++) {
            const int col = bn + wn * 64 + ni * 8 + t4 * 2;
            const long r0 = bm + wm * 64 + mi * 16 + g;
            float2 bb = *(const float2*)&bias[col];
            float2 o0 = { acc[mi][ni][0] + bb.x, acc[mi][ni][1] + bb.y };
            float2 o1 = { acc[mi][ni][2] + bb.x, acc[mi][ni][3] + bb.y };
            *(float2*)&C[r0 * N + col] = o0;
            *(float2*)&C[(r0 + 8) * N + col] = o1;
        }
    }
}

// ---------------------------------------------------------------------------
// QKV GEMM: epilogue writes Q(scaled)/K/V bf16 hi/lo directly to [b,h,s,d].
// ---------------------------------------------------------------------------
__global__ void __launch_bounds__(128, 2) gemm_qkv(
    const __half* __restrict__ Ahi, const __half* __restrict__ Alo,
    const __half* __restrict__ Bh, const float* __restrict__ bias,
    __nv_bfloat16* __restrict__ Qhi, __nv_bfloat16* __restrict__ Qlo,
    __nv_bfloat16* __restrict__ Khi, __nv_bfloat16* __restrict__ Klo,
    __nv_bfloat16* __restrict__ Vhi, __nv_bfloat16* __restrict__ Vlo,
    int K)
{
    GEMM_MAINLOOP(Ahi, Alo, Bh, K)

    const int g  = lane >> 2;
    const int t4 = lane & 3;
    const int region = bn >> 10;            // 0=Q 1=K 2=V
    __nv_bfloat16 *Dhi, *Dlo;
    float scale = 1.f;
    if (region == 0) { Dhi = Qhi; Dlo = Qlo; scale = 0.125f; }
    else if (region == 1) { Dhi = Khi; Dlo = Klo; }
    else { Dhi = Vhi; Dlo = Vlo; }

#pragma unroll
    for (int mi = 0; mi < 4; mi++) {
#pragma unroll
        for (int ni = 0; ni < 8; ni++) {
            const int colg = bn + wn * 64 + ni * 8 + t4 * 2;   // global col
            const int c    = colg & 1023;
            const int h    = c >> 6, d = c & 63;
            const long r0  = bm + wm * 64 + mi * 16 + g;       // = b*S + s
            const int b    = (int)(r0 >> 10);
            const int s    = (int)(r0 & 1023);
            float2 bb = *(const float2*)&bias[colg];
            long o = (((long)b * H_ + h) * S_ + s) * D_ + d;
            __nv_bfloat16 h0, l0, h1, l1;
            split32((acc[mi][ni][0] + bb.x) * scale, h0, l0);
            split32((acc[mi][ni][1] + bb.y) * scale, h1, l1);
            *(__nv_bfloat162*)&Dhi[o] = __nv_bfloat162(h0, h1);
            *(__nv_bfloat162*)&Dlo[o] = __nv_bfloat162(l0, l1);
            split32((acc[mi][ni][2] + bb.x) * scale, h0, l0);
            split32((acc[mi][ni][3] + bb.y) * scale, h1, l1);
            *(__nv_bfloat162*)&Dhi[o + 8 * D_] = __nv_bfloat162(h0, h1);
            *(__nv_bfloat162*)&Dlo[o + 8 * D_] = __nv_bfloat162(l0, l1);
        }
    }
}

// ---------------------------------------------------------------------------
// Causal flash-attention: bf16 3-product HMMA; V in [s][d], PV uses trans-ldsm.
// Epilogue writes fp16 hi/lo directly (proj GEMM input). Unchanged from R9.
// ---------------------------------------------------------------------------
#define ATS 72
#define SST 68

#define Q_HI   0
#define Q_LO   (64 * ATS)
#define K_HI   (2 * 64 * ATS)
#define K_LO   (3 * 64 * ATS)
#define V_HI   (4 * 64 * ATS)
#define V_LO   (5 * 64 * ATS)
#define P_HI   (6 * 64 * ATS)
#define P_LO   (7 * 64 * ATS)
#define S_OFF  (8 * 64 * ATS)
#define ATTN2_SMEM (8 * 64 * ATS * 2 + 64 * SST * 4 + 2 * 64 * 4)

__global__ void __launch_bounds__(256, 2) attn_mma(
    const __nv_bfloat16* __restrict__ Qhi, const __nv_bfloat16* __restrict__ Qlo,
    const __nv_bfloat16* __restrict__ Khi, const __nv_bfloat16* __restrict__ Klo,
    const __nv_bfloat16* __restrict__ Vhi, const __nv_bfloat16* __restrict__ Vlo,
    __half* __restrict__ Ohi, __half* __restrict__ Olo)
{
    extern __shared__ __align__(128) char asmem[];
    __nv_bfloat16* bfs = (__nv_bfloat16*)asmem;
    float* Ss      = (float*)(asmem + S_OFF * 2);
    float* alpha_s = Ss + 64 * SST;
    float* linv_s  = alpha_s + 64;
    const uint32_t sb = smem_to_u32(asmem);

    const int tid  = threadIdx.x;
    const int lane = tid & 31;
    const int wid  = tid >> 5;
    const int wm   = wid & 3;
    const int wn   = wid >> 2;
    const int qt   = blockIdx.x;
    const int h    = blockIdx.y;
    const int b    = blockIdx.z;
    const int q0   = qt * 64;
    const int tx   = tid & 15;
    const int ty   = tid >> 4;

    const long bh = (long)b * H_ + h;

    {
        const __nv_bfloat16* qs[2] = { Qhi + (bh * S_ + q0) * D_,
                                       Qlo + (bh * S_ + q0) * D_ };
#pragma unroll
        for (int j = 0; j < 4; j++) {
            int lin = tid + j * 256;
            int t = lin >> 9;
            int r = (lin >> 3) & 63, c = lin & 7;
            cp_async16(sb + (t ? Q_LO : Q_HI) * 2 + r * (ATS * 2) + c * 16,
                       qs[t] + (long)r * D_ + c * 8);
        }
    }

    float m[4], l[4];
    float oacc[4][4];
#pragma unroll
    for (int i = 0; i < 4; i++) {
        m[i] = -1e30f; l[i] = 0.f;
#pragma unroll
        for (int j = 0; j < 4; j++) oacc[i][j] = 0.f;
    }

    const int arow = wm * 16 + (lane & 15);
    const int asel = (lane >> 4) << 3;
    const int brow = wn * 32 + (lane & 7) + ((lane >> 4) << 3);
    const int bsel = ((lane >> 3) & 1) << 3;
    const int vrow = ((lane >> 3) & 1) * 8 + (lane & 7);
    const int vcol = wn * 32 + ((lane >> 4) << 3);
    const int g    = lane >> 2;
    const int t4   = lane & 3;

    for (int kt = 0; kt <= qt; kt++) {
        __syncthreads();

        {
            const __nv_bfloat16* srcs[4] = {
                Khi + (bh * S_ + kt * 64) * D_, Klo + (bh * S_ + kt * 64) * D_,
                Vhi + (bh * S_ + kt * 64) * D_, Vlo + (bh * S_ + kt * 64) * D_ };
            const uint32_t dof[4] = { K_HI, K_LO, V_HI, V_LO };
#pragma unroll
            for (int j = 0; j < 8; j++) {
                int t = j >> 1;
                int lin = tid + (j & 1) * 256;
                int r = lin >> 3, c = lin & 7;
                cp_async16(sb + dof[t] * 2 + r * (ATS * 2) + c * 16,
                           srcs[t] + (long)r * D_ + c * 8);
            }
        }
        CP_COMMIT();
        CP_WAIT(0);
        __syncthreads();

        float sacc[4][4];
#pragma unroll
        for (int ni = 0; ni < 4; ni++)
#pragma unroll
            for (int r = 0; r < 4; r++) sacc[ni][r] = 0.f;

#pragma unroll
        for (int ks = 0; ks < 4; ks++) {
            const int acol = ks * 16 + asel;
            const int bcol = ks * 16 + bsel;
            uint32_t ah[4], al[4], bh4[4][2], bl4[4][2];
            ldsm_x4(ah[0], ah[1], ah[2], ah[3],
                    sb + (Q_HI + arow * ATS + acol) * 2);
            ldsm_x4(al[0], al[1], al[2], al[3],
                    sb + (Q_LO + arow * ATS + acol) * 2);
#pragma unroll
            for (int nj = 0; nj < 2; nj++) {
                ldsm_x4(bh4[nj * 2][0], bh4[nj * 2][1], bh4[nj * 2 + 1][0], bh4[nj * 2 + 1][1],
                        sb + (K_HI + (brow + nj * 16) * ATS + bcol) * 2);
                ldsm_x4(bl4[nj * 2][0], bl4[nj * 2][1], bl4[nj * 2 + 1][0], bl4[nj * 2 + 1][1],
                        sb + (K_LO + (brow + nj * 16) * ATS + bcol) * 2);
            }
#pragma unroll
            for (int ni = 0; ni < 4; ni++) {
                mma16816(sacc[ni], ah, bh4[ni]);
                mma16816(sacc[ni], ah, bl4[ni]);
                mma16816(sacc[ni], al, bh4[ni]);
            }
        }
#pragma unroll
        for (int ni = 0; ni < 4; ni++) {
            const int col = wn * 32 + ni * 8 + t4 * 2;
            *(float2*)&Ss[(wm * 16 + g) * SST + col]     = make_float2(sacc[ni][0], sacc[ni][1]);
            *(float2*)&Ss[(wm * 16 + g + 8) * SST + col] = make_float2(sacc[ni][2], sacc[ni][3]);
        }
        __syncthreads();

        float s[4][4];
#pragma unroll
        for (int i = 0; i < 4; i++)
#pragma unroll
            for (int j = 0; j < 4; j++)
                s[i][j] = Ss[(ty * 4 + i) * SST + tx * 4 + j];

        if (kt == qt) {
#pragma unroll
            for (int i = 0; i < 4; i++)
#pragma unroll
                for (int j = 0; j < 4; j++)
                    if (tx * 4 + j > ty * 4 + i) s[i][j] = -1e9f;
        }

#pragma unroll
        for (int i = 0; i < 4; i++) {
            float mx = fmaxf(fmaxf(s[i][0], s[i][1]), fmaxf(s[i][2], s[i][3]));
#pragma unroll
            for (int off = 8; off > 0; off >>= 1)
                mx = fmaxf(mx, __shfl_xor_sync(0xffffffffu, mx, off));
            float mnew = fmaxf(m[i], mx);
            float alpha = __expf(m[i] - mnew);
            m[i] = mnew;
            float rs = 0.f;
#pragma unroll
            for (int j = 0; j < 4; j++) {
                s[i][j] = __expf(s[i][j] - mnew);
                rs += s[i][j];
            }
#pragma unroll
            for (int off = 8; off > 0; off >>= 1)
                rs += __shfl_xor_sync(0xffffffffu, rs, off);
            l[i] = l[i] * alpha + rs;
            if (tx == 0) alpha_s[ty * 4 + i] = alpha;
            const int pr = (ty * 4 + i) * ATS + tx * 4;
#pragma unroll
            for (int j = 0; j < 4; j += 2) {
                __nv_bfloat16 h0, l0, h1, l1;
                split32(s[i][j], h0, l0);
                split32(s[i][j + 1], h1, l1);
                *(__nv_bfloat162*)&bfs[P_HI + pr + j] = __nv_bfloat162(h0, h1);
                *(__nv_bfloat162*)&bfs[P_LO + pr + j] = __nv_bfloat162(l0, l1);
            }
        }
        __syncthreads();

        const float al0 = alpha_s[wm * 16 + g];
        const float al1 = alpha_s[wm * 16 + g + 8];
#pragma unroll
        for (int ni = 0; ni < 4; ni++) {
            oacc[ni][0] *= al0; oacc[ni][1] *= al0;
            oacc[ni][2] *= al1; oacc[ni][3] *= al1;
        }
#pragma unroll
        for (int ks = 0; ks < 4; ks++) {
            const int acol = ks * 16 + asel;
            uint32_t ah[4], al[4], bh4[4][2], bl4[4][2];
            ldsm_x4(ah[0], ah[1], ah[2], ah[3],
                    sb + (P_HI + arow * ATS + acol) * 2);
            ldsm_x4(al[0], al[1], al[2], al[3],
                    sb + (P_LO + arow * ATS + acol) * 2);
#pragma unroll
            for (int nj = 0; nj < 2; nj++) {
                const uint32_t vaddr = (ks * 16 + vrow) * ATS + vcol + nj * 16;
                ldsm_x4t(bh4[nj * 2][0], bh4[nj * 2][1], bh4[nj * 2 + 1][0], bh4[nj * 2 + 1][1],
                         sb + (V_HI + vaddr) * 2);
                ldsm_x4t(bl4[nj * 2][0], bl4[nj * 2][1], bl4[nj * 2 + 1][0], bl4[nj * 2 + 1][1],
                         sb + (V_LO + vaddr) * 2);
            }
#pragma unroll
            for (int ni = 0; ni < 4; ni++) {
                mma16816(oacc[ni], ah, bh4[ni]);
                mma16816(oacc[ni], ah, bl4[ni]);
                mma16816(oacc[ni], al, bh4[ni]);
            }
        }
    }

#pragma unroll
    for (int i = 0; i < 4; i++)
        if (tx == 0) linv_s[ty * 4 + i] = 1.f / l[i];
    __syncthreads();

    const float li0 = linv_s[wm * 16 + g];
    const float li1 = linv_s[wm * 16 + g + 8];
#pragma unroll
    for (int ni = 0; ni < 4; ni++) {
        const int col = h * D_ + wn * 32 + ni * 8 + t4 * 2;
        const long r0 = (long)b * S_ + q0 + wm * 16 + g;
        __half h0, l0, h1, l1;
        split16(oacc[ni][0] * li0, h0, l0);
        split16(oacc[ni][1] * li0, h1, l1);
        *(__half2*)&Ohi[r0 * NX_ + col] = __half2(h0, h1);
        *(__half2*)&Olo[r0 * NX_ + col] = __half2(l0, l1);
        split16(oacc[ni][2] * li1, h0, l0);
        split16(oacc[ni][3] * li1, h1, l1);
        *(__half2*)&Ohi[(r0 + 8) * NX_ + col] = __half2(h0, h1);
        *(__half2*)&Olo[(r0 + 8) * NX_ + col] = __half2(l0, l1);
    }
}

// ---------------------------------------------------------------------------
extern "C" void kernel_launch(void* const* d_in, const int* in_sizes, int n_in,
                              void* d_out, int out_size)
{
    const float* x      = (const float*)d_in[0];
    const float* w_attn = (const float*)d_in[1];
    const float* b_attn = (const float*)d_in[2];
    const float* w_proj = (const float*)d_in[3];
    const float* b_proj = (const float*)d_in[4];
    float* out = (float*)d_out;

    __half *xhi, *xlo, *ahi, *alo, *wqh, *wph;
    __nv_bfloat16 *qhi, *qlo, *khi, *klo, *vhi, *vlo;
    cudaGetSymbolAddress((void**)&xhi, g_xhi);
    cudaGetSymbolAddress((void**)&xlo, g_xlo);
    cudaGetSymbolAddress((void**)&ahi, g_ahi);
    cudaGetSymbolAddress((void**)&alo, g_alo);
    cudaGetSymbolAddress((void**)&wqh, g_wqkv_h);
    cudaGetSymbolAddress((void**)&wph, g_wproj_h);
    cudaGetSymbolAddress((void**)&qhi, g_qhi);
    cudaGetSymbolAddress((void**)&qlo, g_qlo);
    cudaGetSymbolAddress((void**)&khi, g_khi);
    cudaGetSymbolAddress((void**)&klo, g_klo);
    cudaGetSymbolAddress((void**)&vhi, g_vhi);
    cudaGetSymbolAddress((void**)&vlo, g_vlo);

    cudaFuncSetAttribute(attn_mma,
                         cudaFuncAttributeMaxDynamicSharedMemorySize, ATTN2_SMEM);
    cudaFuncSetAttribute(gemm_qkv,
                         cudaFuncAttributeMaxDynamicSharedMemorySize, GEMM_SMEM_DYN);
    cudaFuncSetAttribute(gemm_proj,
                         cudaFuncAttributeMaxDynamicSharedMemorySize, GEMM_SMEM_DYN);

    const int M = B_ * S_;  // 8192

    // split x (fp16 hi/lo)
    {
        int n4 = M * NX_ / 4;
        split_kernel<<<(n4 + 255) / 256, 256>>>(x, xhi, xlo, n4);
    }
    // transpose+truncate weights (fp16)
    tsplit_kernel<<<dim3(3 * NX_ / 32, NX_ / 32), dim3(32, 8)>>>(w_attn, wqh, NX_, 3 * NX_);
    tsplit_kernel<<<dim3(NX_ / 32, NX_ / 32), dim3(32, 8)>>>(w_proj, wph, NX_, NX_);

    // QKV GEMM with fused split epilogue -> q/k/v bf16 hi/lo [b,h,s,d]
    gemm_qkv<<<dim3(3 * NX_ / 128, M / 128), 128, GEMM_SMEM_DYN>>>(
        xhi, xlo, wqh, b_attn, qhi, qlo, khi, klo, vhi, vlo, NX_);

    // attention (bf16 3-product HMMA) -> fp16 hi/lo directly
    attn_mma<<<dim3(S_ / 64, H_, B_), 256, ATTN2_SMEM>>>(
        qhi, qlo, khi, klo, vhi, vlo, ahi, alo);

    // projection GEMM -> final fp32 output
    gemm_proj<<<dim3(NX_ / 128, M / 128), 128, GEMM_SMEM_DYN>>>(
        ahi, alo, wph, b_proj, out, NX_, NX_);
}

// round 11
// speedup vs baseline: 1.3672x; 1.3672x over previous
#include <cuda_runtime.h>
#include <cuda_bf16.h>
#include <cuda_fp16.h>
#include <cstdint>

#define B_  8
#define S_  1024
#define NX_ 1024
#define H_  16
#define D_  64

// ---------------- scratch (__device__ globals; no allocation) ----------------
__device__ __half g_xh[B_ * S_ * NX_];               // x, fp16 trunc
__device__ __half g_ah[B_ * S_ * NX_];               // attention out, fp16 trunc
__device__ __half g_wqkv_h[3 * NX_ * NX_];           // [N=3072, K=1024] fp16 trunc
__device__ __half g_wproj_h[NX_ * NX_];              // [N=1024, K=1024]
// attention operands, written by QKV GEMM epilogue: bf16 hi/lo, [b,h,s,d]
__device__ __nv_bfloat16 g_qhi[B_ * H_ * S_ * D_];   // pre-scaled by 0.125
__device__ __nv_bfloat16 g_qlo[B_ * H_ * S_ * D_];
__device__ __nv_bfloat16 g_khi[B_ * H_ * S_ * D_];
__device__ __nv_bfloat16 g_klo[B_ * H_ * S_ * D_];
__device__ __nv_bfloat16 g_vhi[B_ * H_ * S_ * D_];
__device__ __nv_bfloat16 g_vlo[B_ * H_ * S_ * D_];

// ---------------- PTX helpers ----------------
__device__ __forceinline__ uint32_t smem_to_u32(const void* p) {
    uint32_t a;
    asm("{ .reg .u64 t; cvta.to.shared.u64 t, %1; cvt.u32.u64 %0, t; }"
        : "=r"(a) : "l"(p));
    return a;
}
__device__ __forceinline__ void cp_async16(uint32_t dst, const void* src) {
    asm volatile("cp.async.cg.shared.global [%0], [%1], 16;"
                 :: "r"(dst), "l"(src) : "memory");
}
#define CP_COMMIT() asm volatile("cp.async.commit_group;" ::: "memory")
#define CP_WAIT(n)  asm volatile("cp.async.wait_group %0;" :: "n"(n) : "memory")

__device__ __forceinline__ void ldsm_x4(uint32_t& r0, uint32_t& r1,
                                        uint32_t& r2, uint32_t& r3, uint32_t addr) {
    asm volatile("ldmatrix.sync.aligned.m8n8.x4.shared.b16 {%0,%1,%2,%3}, [%4];"
                 : "=r"(r0), "=r"(r1), "=r"(r2), "=r"(r3) : "r"(addr));
}
__device__ __forceinline__ void ldsm_x4t(uint32_t& r0, uint32_t& r1,
                                         uint32_t& r2, uint32_t& r3, uint32_t addr) {
    asm volatile("ldmatrix.sync.aligned.m8n8.x4.trans.shared.b16 {%0,%1,%2,%3}, [%4];"
                 : "=r"(r0), "=r"(r1), "=r"(r2), "=r"(r3) : "r"(addr));
}
// bf16 MMA (attention)
__device__ __forceinline__ void mma16816(float* c, const uint32_t* a, const uint32_t* b) {
    asm volatile("mma.sync.aligned.m16n8k16.row.col.f32.bf16.bf16.f32 "
                 "{%0,%1,%2,%3}, {%4,%5,%6,%7}, {%8,%9}, {%0,%1,%2,%3};"
                 : "+f"(c[0]), "+f"(c[1]), "+f"(c[2]), "+f"(c[3])
                 : "r"(a[0]), "r"(a[1]), "r"(a[2]), "r"(a[3]),
                   "r"(b[0]), "r"(b[1]));
}
// fp16 MMA (GEMMs)
__device__ __forceinline__ void mma16816h(float* c, const uint32_t* a, const uint32_t* b) {
    asm volatile("mma.sync.aligned.m16n8k16.row.col.f32.f16.f16.f32 "
                 "{%0,%1,%2,%3}, {%4,%5,%6,%7}, {%8,%9}, {%0,%1,%2,%3};"
                 : "+f"(c[0]), "+f"(c[1]), "+f"(c[2]), "+f"(c[3])
                 : "r"(a[0]), "r"(a[1]), "r"(a[2]), "r"(a[3]),
                   "r"(b[0]), "r"(b[1]));
}
__device__ __forceinline__ void split32(float v, __nv_bfloat16& h, __nv_bfloat16& l) {
    h = __float2bfloat16(v);
    l = __float2bfloat16(v - __bfloat162float(h));
}

// ---------------------------------------------------------------------------
// truncate: fp32 -> fp16, same layout.
// ---------------------------------------------------------------------------
__global__ void trunc_kernel(const float* __restrict__ in,
                             __half* __restrict__ h, int n4)
{
    int i = blockIdx.x * blockDim.x + threadIdx.x;
    if (i >= n4) return;
    float4 v = ((const float4*)in)[i];
    ((__half2*)h)[2 * i]     = __half2(__float2half(v.x), __float2half(v.y));
    ((__half2*)h)[2 * i + 1] = __half2(__float2half(v.z), __float2half(v.w));
}

// ---------------------------------------------------------------------------
// transpose + truncate: W[K,N] fp32 -> T_h [N,K] fp16
// ---------------------------------------------------------------------------
__global__ void tsplit_kernel(const float* __restrict__ W,
                              __half* __restrict__ Th, int K, int N)
{
    __shared__ float t[32][33];
    int n0 = blockIdx.x * 32, k0 = blockIdx.y * 32;
    int tx = threadIdx.x, ty = threadIdx.y;  // 32 x 8
#pragma unroll
    for (int i = 0; i < 4; i++)
        t[ty + i * 8][tx] = W[(long)(k0 + ty + i * 8) * N + n0 + tx];
    __syncthreads();
#pragma unroll
    for (int i = 0; i < 4; i++) {
        float v = t[tx][ty + i * 8];
        Th[(long)(n0 + ty + i * 8) * K + k0 + tx] = __float2half(v);
    }
}

// ---------------------------------------------------------------------------
// Shared GEMM mainloop: single-product fp16, 128x128x32 CTA tile, 256 threads,
// 8 warps (2Mx4N), 64x32 warp tile, 4-stage cp.async pipeline.
// ---------------------------------------------------------------------------
#define ROWB    80
#define TILE_B  (128 * ROWB)             // 10240 B
#define STAGE_B (2 * TILE_B)             // Ah Bh = 20480 B
#define NSTAGE  4
#define GEMM_SMEM_DYN (NSTAGE * STAGE_B) // 81920 B

#define GEMM_MAINLOOP(Ah, Bh, K)                                                \
    extern __shared__ __align__(128) char smem[];                               \
    const uint32_t sbase = smem_to_u32(smem);                                   \
    const int tid  = threadIdx.x;                                               \
    const int lane = tid & 31;                                                  \
    const int wid  = tid >> 5;                                                  \
    const int wm   = wid & 1;                                                   \
    const int wn   = wid >> 1;                                                  \
    const int bm   = blockIdx.y * 128;                                          \
    const int bn   = blockIdx.x * 128;                                          \
    float acc[4][4][4];                                                         \
    _Pragma("unroll")                                                           \
    for (int mi = 0; mi < 4; mi++)                                              \
        _Pragma("unroll")                                                       \
        for (int ni = 0; ni < 4; ni++)                                          \
            _Pragma("unroll")                                                   \
            for (int r = 0; r < 4; r++) acc[mi][ni][r] = 0.f;                   \
    const int row = tid & 127;                                                  \
    const int ch  = tid >> 7;                                                   \
    const __half* gA = Ah + (long)bm * (K);                                     \
    const __half* gB = Bh + (long)bn * (K);                                     \
    const int NS = (K) / 32;                                                    \
    auto load_stage = [&](int s) {                                              \
        const int k0 = s * 32;                                                  \
        const uint32_t buf = sbase + (s % NSTAGE) * STAGE_B;                    \
        _Pragma("unroll")                                                       \
        for (int j = 0; j < 2; j++) {                                           \
            int c = ch + 2 * j;                                                 \
            cp_async16(buf + row * ROWB + c * 16,                               \
                       gA + (long)row * (K) + k0 + c * 8);                      \
            cp_async16(buf + TILE_B + row * ROWB + c * 16,                      \
                       gB + (long)row * (K) + k0 + c * 8);                      \
        }                                                                       \
    };                                                                          \
    load_stage(0);                                                              \
    CP_COMMIT();                                                                \
    load_stage(1);                                                              \
    CP_COMMIT();                                                                \
    load_stage(2);                                                              \
    CP_COMMIT();                                                                \
    const int arow  = wm * 64 + (lane & 15);                                    \
    const int asel  = (lane >> 4) << 3;                                         \
    const int brow  = wn * 32 + (lane & 7) + ((lane >> 4) << 3);                \
    const int bsel  = ((lane >> 3) & 1) << 3;                                   \
    for (int s = 0; s < NS; s++) {                                              \
        if (s + 3 < NS) {                                                       \
            load_stage(s + 3);                                                  \
            CP_COMMIT();                                                        \
            CP_WAIT(3);                                                         \
        } else {                                                                \
            CP_WAIT(0);                                                         \
        }                                                                       \
        __syncthreads();                                                        \
        const uint32_t buf = sbase + (s % NSTAGE) * STAGE_B;                    \
        _Pragma("unroll")                                                       \
        for (int ks = 0; ks < 2; ks++) {                                        \
            uint32_t a[4][4];                                                   \
            uint32_t b[4][2];                                                   \
            const int acol = ks * 16 + asel;                                    \
            const int bcol = ks * 16 + bsel;                                    \
            _Pragma("unroll")                                                   \
            for (int nj = 0; nj < 2; nj++)                                      \
                ldsm_x4(b[nj * 2][0], b[nj * 2][1],                             \
                        b[nj * 2 + 1][0], b[nj * 2 + 1][1],                     \
                        buf + TILE_B + (brow + nj * 16) * ROWB + bcol * 2);     \
            _Pragma("unroll")                                                   \
            for (int mi = 0; mi < 4; mi++)                                      \
                ldsm_x4(a[mi][0], a[mi][1], a[mi][2], a[mi][3],                 \
                        buf + (arow + mi * 16) * ROWB + acol * 2);              \
            _Pragma("unroll")                                                   \
            for (int mi = 0; mi < 4; mi++)                                      \
                _Pragma("unroll")                                               \
                for (int ni = 0; ni < 4; ni++)                                  \
                    mma16816h(acc[mi][ni], a[mi], b[ni]);                       \
        }                                                                       \
        __syncthreads();                                                        \
    }

// ---------------------------------------------------------------------------
// Projection GEMM: fp32 out + bias (final output)
// ---------------------------------------------------------------------------
__global__ void __launch_bounds__(256, 2) gemm_proj(
    const __half* __restrict__ Ah, const __half* __restrict__ Bh,
    const float* __restrict__ bias, float* __restrict__ C, int N, int K)
{
    GEMM_MAINLOOP(Ah, Bh, K)

    const int g  = lane >> 2;
    const int t4 = lane & 3;
#pragma unroll
    for (int mi = 0; mi < 4; mi++) {
#pragma unroll
        for (int ni = 0; ni < 4; ni++) {
            const int col = bn + wn * 32 + ni * 8 + t4 * 2;
            const long r0 = bm + wm * 64 + mi * 16 + g;
            float2 bb = *(const float2*)&bias[col];
            float2 o0 = { acc[mi][ni][0] + bb.x, acc[mi][ni][1] + bb.y };
            float2 o1 = { acc[mi][ni][2] + bb.x, acc[mi][ni][3] + bb.y };
            *(float2*)&C[r0 * N + col] = o0;
            *(float2*)&C[(r0 + 8) * N + col] = o1;
        }
    }
}

// ---------------------------------------------------------------------------
// QKV GEMM: epilogue writes Q(scaled)/K/V bf16 hi/lo directly to [b,h,s,d].
// ---------------------------------------------------------------------------
__global__ void __launch_bounds__(256, 2) gemm_qkv(
    const __half* __restrict__ Ah, const __half* __restrict__ Bh,
    const float* __restrict__ bias,
    __nv_bfloat16* __restrict__ Qhi, __nv_bfloat16* __restrict__ Qlo,
    __nv_bfloat16* __restrict__ Khi, __nv_bfloat16* __restrict__ Klo,
    __nv_bfloat16* __restrict__ Vhi, __nv_bfloat16* __restrict__ Vlo,
    int K)
{
    GEMM_MAINLOOP(Ah, Bh, K)

    const int g  = lane >> 2;
    const int t4 = lane & 3;
    const int region = bn >> 10;            // 0=Q 1=K 2=V
    __nv_bfloat16 *Dhi, *Dlo;
    float scale = 1.f;
    if (region == 0) { Dhi = Qhi; Dlo = Qlo; scale = 0.125f; }
    else if (region == 1) { Dhi = Khi; Dlo = Klo; }
    else { Dhi = Vhi; Dlo = Vlo; }

#pragma unroll
    for (int mi = 0; mi < 4; mi++) {
#pragma unroll
        for (int ni = 0; ni < 4; ni++) {
            const int colg = bn + wn * 32 + ni * 8 + t4 * 2;
            const int c    = colg & 1023;
            const int h    = c >> 6, d = c & 63;
            const long r0  = bm + wm * 64 + mi * 16 + g;       // = b*S + s
            const int b    = (int)(r0 >> 10);
            const int s    = (int)(r0 & 1023);
            float2 bb = *(const float2*)&bias[colg];
            long o = (((long)b * H_ + h) * S_ + s) * D_ + d;
            __nv_bfloat16 h0, l0, h1, l1;
            split32((acc[mi][ni][0] + bb.x) * scale, h0, l0);
            split32((acc[mi][ni][1] + bb.y) * scale, h1, l1);
            *(__nv_bfloat162*)&Dhi[o] = __nv_bfloat162(h0, h1);
            *(__nv_bfloat162*)&Dlo[o] = __nv_bfloat162(l0, l1);
            split32((acc[mi][ni][2] + bb.x) * scale, h0, l0);
            split32((acc[mi][ni][3] + bb.y) * scale, h1, l1);
            *(__nv_bfloat162*)&Dhi[o + 8 * D_] = __nv_bfloat162(h0, h1);
            *(__nv_bfloat162*)&Dlo[o + 8 * D_] = __nv_bfloat162(l0, l1);
        }
    }
}

// ---------------------------------------------------------------------------
// Causal flash-attention: bf16 3-product HMMA; V in [s][d], PV uses trans-ldsm.
// Epilogue writes fp16 (trunc) directly as proj GEMM input.
// ---------------------------------------------------------------------------
#define ATS 72
#define SST 68

#define Q_HI   0
#define Q_LO   (64 * ATS)
#define K_HI   (2 * 64 * ATS)
#define K_LO   (3 * 64 * ATS)
#define V_HI   (4 * 64 * ATS)
#define V_LO   (5 * 64 * ATS)
#define P_HI   (6 * 64 * ATS)
#define P_LO   (7 * 64 * ATS)
#define S_OFF  (8 * 64 * ATS)
#define ATTN2_SMEM (8 * 64 * ATS * 2 + 64 * SST * 4 + 2 * 64 * 4)

__global__ void __launch_bounds__(256, 2) attn_mma(
    const __nv_bfloat16* __restrict__ Qhi, const __nv_bfloat16* __restrict__ Qlo,
    const __nv_bfloat16* __restrict__ Khi, const __nv_bfloat16* __restrict__ Klo,
    const __nv_bfloat16* __restrict__ Vhi, const __nv_bfloat16* __restrict__ Vlo,
    __half* __restrict__ Oh)
{
    extern __shared__ __align__(128) char asmem[];
    __nv_bfloat16* bfs = (__nv_bfloat16*)asmem;
    float* Ss      = (float*)(asmem + S_OFF * 2);
    float* alpha_s = Ss + 64 * SST;
    float* linv_s  = alpha_s + 64;
    const uint32_t sb = smem_to_u32(asmem);

    const int tid  = threadIdx.x;
    const int lane = tid & 31;
    const int wid  = tid >> 5;
    const int wm   = wid & 3;
    const int wn   = wid >> 2;
    const int qt   = blockIdx.x;
    const int h    = blockIdx.y;
    const int b    = blockIdx.z;
    const int q0   = qt * 64;
    const int tx   = tid & 15;
    const int ty   = tid >> 4;

    const long bh = (long)b * H_ + h;

    {
        const __nv_bfloat16* qs[2] = { Qhi + (bh * S_ + q0) * D_,
                                       Qlo + (bh * S_ + q0) * D_ };
#pragma unroll
        for (int j = 0; j < 4; j++) {
            int lin = tid + j * 256;
            int t = lin >> 9;
            int r = (lin >> 3) & 63, c = lin & 7;
            cp_async16(sb + (t ? Q_LO : Q_HI) * 2 + r * (ATS * 2) + c * 16,
                       qs[t] + (long)r * D_ + c * 8);
        }
    }

    float m[4], l[4];
    float oacc[4][4];
#pragma unroll
    for (int i = 0; i < 4; i++) {
        m[i] = -1e30f; l[i] = 0.f;
#pragma unroll
        for (int j = 0; j < 4; j++) oacc[i][j] = 0.f;
    }

    const int arow = wm * 16 + (lane & 15);
    const int asel = (lane >> 4) << 3;
    const int brow = wn * 32 + (lane & 7) + ((lane >> 4) << 3);
    const int bsel = ((lane >> 3) & 1) << 3;
    const int vrow = ((lane >> 3) & 1) * 8 + (lane & 7);
    const int vcol = wn * 32 + ((lane >> 4) << 3);
    const int g    = lane >> 2;
    const int t4   = lane & 3;

    for (int kt = 0; kt <= qt; kt++) {
        __syncthreads();

        {
            const __nv_bfloat16* srcs[4] = {
                Khi + (bh * S_ + kt * 64) * D_, Klo + (bh * S_ + kt * 64) * D_,
                Vhi + (bh * S_ + kt * 64) * D_, Vlo + (bh * S_ + kt * 64) * D_ };
            const uint32_t dof[4] = { K_HI, K_LO, V_HI, V_LO };
#pragma unroll
            for (int j = 0; j < 8; j++) {
                int t = j >> 1;
                int lin = tid + (j & 1) * 256;
                int r = lin >> 3, c = lin & 7;
                cp_async16(sb + dof[t] * 2 + r * (ATS * 2) + c * 16,
                           srcs[t] + (long)r * D_ + c * 8);
            }
        }
        CP_COMMIT();
        CP_WAIT(0);
        __syncthreads();

        float sacc[4][4];
#pragma unroll
        for (int ni = 0; ni < 4; ni++)
#pragma unroll
            for (int r = 0; r < 4; r++) sacc[ni][r] = 0.f;

#pragma unroll
        for (int ks = 0; ks < 4; ks++) {
            const int acol = ks * 16 + asel;
            const int bcol = ks * 16 + bsel;
            uint32_t ah[4], al[4], bh4[4][2], bl4[4][2];
            ldsm_x4(ah[0], ah[1], ah[2], ah[3],
                    sb + (Q_HI + arow * ATS + acol) * 2);
            ldsm_x4(al[0], al[1], al[2], al[3],
                    sb + (Q_LO + arow * ATS + acol) * 2);
#pragma unroll
            for (int nj = 0; nj < 2; nj++) {
                ldsm_x4(bh4[nj * 2][0], bh4[nj * 2][1], bh4[nj * 2 + 1][0], bh4[nj * 2 + 1][1],
                        sb + (K_HI + (brow + nj * 16) * ATS + bcol) * 2);
                ldsm_x4(bl4[nj * 2][0], bl4[nj * 2][1], bl4[nj * 2 + 1][0], bl4[nj * 2 + 1][1],
                        sb + (K_LO + (brow + nj * 16) * ATS + bcol) * 2);
            }
#pragma unroll
            for (int ni = 0; ni < 4; ni++) {
                mma16816(sacc[ni], ah, bh4[ni]);
                mma16816(sacc[ni], ah, bl4[ni]);
                mma16816(sacc[ni], al, bh4[ni]);
            }
        }
#pragma unroll
        for (int ni = 0; ni < 4; ni++) {
            const int col = wn * 32 + ni * 8 + t4 * 2;
            *(float2*)&Ss[(wm * 16 + g) * SST + col]     = make_float2(sacc[ni][0], sacc[ni][1]);
            *(float2*)&Ss[(wm * 16 + g + 8) * SST + col] = make_float2(sacc[ni][2], sacc[ni][3]);
        }
        __syncthreads();

        float s[4][4];
#pragma unroll
        for (int i = 0; i < 4; i++)
#pragma unroll
            for (int j = 0; j < 4; j++)
                s[i][j] = Ss[(ty * 4 + i) * SST + tx * 4 + j];

        if (kt == qt) {
#pragma unroll
            for (int i = 0; i < 4; i++)
#pragma unroll
                for (int j = 0; j < 4; j++)
                    if (tx * 4 + j > ty * 4 + i) s[i][j] = -1e9f;
        }

#pragma unroll
        for (int i = 0; i < 4; i++) {
            float mx = fmaxf(fmaxf(s[i][0], s[i][1]), fmaxf(s[i][2], s[i][3]));
#pragma unroll
            for (int off = 8; off > 0; off >>= 1)
                mx = fmaxf(mx, __shfl_xor_sync(0xffffffffu, mx, off));
            float mnew = fmaxf(m[i], mx);
            float alpha = __expf(m[i] - mnew);
            m[i] = mnew;
            float rs = 0.f;
#pragma unroll
            for (int j = 0; j < 4; j++) {
                s[i][j] = __expf(s[i][j] - mnew);
                rs += s[i][j];
            }
#pragma unroll
            for (int off = 8; off > 0; off >>= 1)
                rs += __shfl_xor_sync(0xffffffffu, rs, off);
            l[i] = l[i] * alpha + rs;
            if (tx == 0) alpha_s[ty * 4 + i] = alpha;
            const int pr = (ty * 4 + i) * ATS + tx * 4;
#pragma unroll
            for (int j = 0; j < 4; j += 2) {
                __nv_bfloat16 h0, l0, h1, l1;
                split32(s[i][j], h0, l0);
                split32(s[i][j + 1], h1, l1);
                *(__nv_bfloat162*)&bfs[P_HI + pr + j] = __nv_bfloat162(h0, h1);
                *(__nv_bfloat162*)&bfs[P_LO + pr + j] = __nv_bfloat162(l0, l1);
            }
        }
        __syncthreads();

        const float al0 = alpha_s[wm * 16 + g];
        const float al1 = alpha_s[wm * 16 + g + 8];
#pragma unroll
        for (int ni = 0; ni < 4; ni++) {
            oacc[ni][0] *= al0; oacc[ni][1] *= al0;
            oacc[ni][2] *= al1; oacc[ni][3] *= al1;
        }
#pragma unroll
        for (int ks = 0; ks < 4; ks++) {
            const int acol = ks * 16 + asel;
            uint32_t ah[4], al[4], bh4[4][2], bl4[4][2];
            ldsm_x4(ah[0], ah[1], ah[2], ah[3],
                    sb + (P_HI + arow * ATS + acol) * 2);
            ldsm_x4(al[0], al[1], al[2], al[3],
                    sb + (P_LO + arow * ATS + acol) * 2);
#pragma unroll
            for (int nj = 0; nj < 2; nj++) {
                const uint32_t vaddr = (ks * 16 + vrow) * ATS + vcol + nj * 16;
                ldsm_x4t(bh4[nj * 2][0], bh4[nj * 2][1], bh4[nj * 2 + 1][0], bh4[nj * 2 + 1][1],
                         sb + (V_HI + vaddr) * 2);
                ldsm_x4t(bl4[nj * 2][0], bl4[nj * 2][1], bl4[nj * 2 + 1][0], bl4[nj * 2 + 1][1],
                         sb + (V_LO + vaddr) * 2);
            }
#pragma unroll
            for (int ni = 0; ni < 4; ni++) {
                mma16816(oacc[ni], ah, bh4[ni]);
                mma16816(oacc[ni], ah, bl4[ni]);
                mma16816(oacc[ni], al, bh4[ni]);
            }
        }
    }

#pragma unroll
    for (int i = 0; i < 4; i++)
        if (tx == 0) linv_s[ty * 4 + i] = 1.f / l[i];
    __syncthreads();

    const float li0 = linv_s[wm * 16 + g];
    const float li1 = linv_s[wm * 16 + g + 8];
#pragma unroll
    for (int ni = 0; ni < 4; ni++) {
        const int col = h * D_ + wn * 32 + ni * 8 + t4 * 2;
        const long r0 = (long)b * S_ + q0 + wm * 16 + g;
        *(__half2*)&Oh[r0 * NX_ + col] =
            __half2(__float2half(oacc[ni][0] * li0), __float2half(oacc[ni][1] * li0));
        *(__half2*)&Oh[(r0 + 8) * NX_ + col] =
            __half2(__float2half(oacc[ni][2] * li1), __float2half(oacc[ni][3] * li1));
    }
}

// ---------------------------------------------------------------------------
extern "C" void kernel_launch(void* const* d_in, const int* in_sizes, int n_in,
                              void* d_out, int out_size)
{
    const float* x      = (const float*)d_in[0];
    const float* w_attn = (const float*)d_in[1];
    const float* b_attn = (const float*)d_in[2];
    const float* w_proj = (const float*)d_in[3];
    const float* b_proj = (const float*)d_in[4];
    float* out = (float*)d_out;

    __half *xh, *ah, *wqh, *wph;
    __nv_bfloat16 *qhi, *qlo, *khi, *klo, *vhi, *vlo;
    cudaGetSymbolAddress((void**)&xh, g_xh);
    cudaGetSymbolAddress((void**)&ah, g_ah);
    cudaGetSymbolAddress((void**)&wqh, g_wqkv_h);
    cudaGetSymbolAddress((void**)&wph, g_wproj_h);
    cudaGetSymbolAddress((void**)&qhi, g_qhi);
    cudaGetSymbolAddress((void**)&qlo, g_qlo);
    cudaGetSymbolAddress((void**)&khi, g_khi);
    cudaGetSymbolAddress((void**)&klo, g_klo);
    cudaGetSymbolAddress((void**)&vhi, g_vhi);
    cudaGetSymbolAddress((void**)&vlo, g_vlo);

    cudaFuncSetAttribute(attn_mma,
                         cudaFuncAttributeMaxDynamicSharedMemorySize, ATTN2_SMEM);
    cudaFuncSetAttribute(gemm_qkv,
                         cudaFuncAttributeMaxDynamicSharedMemorySize, GEMM_SMEM_DYN);
    cudaFuncSetAttribute(gemm_proj,
                         cudaFuncAttributeMaxDynamicSharedMemorySize, GEMM_SMEM_DYN);

    const int M = B_ * S_;  // 8192

    // truncate x to fp16
    {
        int n4 = M * NX_ / 4;
        trunc_kernel<<<(n4 + 255) / 256, 256>>>(x, xh, n4);
    }
    // transpose+truncate weights (fp16)
    tsplit_kernel<<<dim3(3 * NX_ / 32, NX_ / 32), dim3(32, 8)>>>(w_attn, wqh, NX_, 3 * NX_);
    tsplit_kernel<<<dim3(NX_ / 32, NX_ / 32), dim3(32, 8)>>>(w_proj, wph, NX_, NX_);

    // QKV GEMM (single-product fp16) with fused split epilogue
    gemm_qkv<<<dim3(3 * NX_ / 128, M / 128), 256, GEMM_SMEM_DYN>>>(
        xh, wqh, b_attn, qhi, qlo, khi, klo, vhi, vlo, NX_);

    // attention (bf16 3-product HMMA) -> fp16 trunc
    attn_mma<<<dim3(S_ / 64, H_, B_), 256, ATTN2_SMEM>>>(
        qhi, qlo, khi, klo, vhi, vlo, ah);

    // projection GEMM (single-product fp16) -> final fp32 output
    gemm_proj<<<dim3(NX_ / 128, M / 128), 256, GEMM_SMEM_DYN>>>(
        ah, wph, b_proj, out, NX_, NX_);
}

// round 12
// speedup vs baseline: 1.5943x; 1.1661x over previous
#include <cuda_runtime.h>
#include <cuda_bf16.h>
#include <cuda_fp16.h>
#include <cstdint>

#define B_  8
#define S_  1024
#define NX_ 1024
#define H_  16
#define D_  64

// ---------------- scratch (__device__ globals; no allocation) ----------------
__device__ __half g_xh[B_ * S_ * NX_];               // x, fp16 trunc
__device__ __half g_ah[B_ * S_ * NX_];               // attention out, fp16 trunc
__device__ __half g_wqkv_h[3 * NX_ * NX_];           // [N=3072, K=1024] fp16 trunc
__device__ __half g_wproj_h[NX_ * NX_];              // [N=1024, K=1024]
// attention operands, fp16 trunc, [b,h,s,d], written by QKV GEMM epilogue
__device__ __half g_qh[B_ * H_ * S_ * D_];           // pre-scaled by 0.125
__device__ __half g_kh[B_ * H_ * S_ * D_];
__device__ __half g_vh[B_ * H_ * S_ * D_];

// ---------------- PTX helpers ----------------
__device__ __forceinline__ uint32_t smem_to_u32(const void* p) {
    uint32_t a;
    asm("{ .reg .u64 t; cvta.to.shared.u64 t, %1; cvt.u32.u64 %0, t; }"
        : "=r"(a) : "l"(p));
    return a;
}
__device__ __forceinline__ void cp_async16(uint32_t dst, const void* src) {
    asm volatile("cp.async.cg.shared.global [%0], [%1], 16;"
                 :: "r"(dst), "l"(src) : "memory");
}
#define CP_COMMIT() asm volatile("cp.async.commit_group;" ::: "memory")
#define CP_WAIT(n)  asm volatile("cp.async.wait_group %0;" :: "n"(n) : "memory")

__device__ __forceinline__ void ldsm_x4(uint32_t& r0, uint32_t& r1,
                                        uint32_t& r2, uint32_t& r3, uint32_t addr) {
    asm volatile("ldmatrix.sync.aligned.m8n8.x4.shared.b16 {%0,%1,%2,%3}, [%4];"
                 : "=r"(r0), "=r"(r1), "=r"(r2), "=r"(r3) : "r"(addr));
}
__device__ __forceinline__ void ldsm_x4t(uint32_t& r0, uint32_t& r1,
                                         uint32_t& r2, uint32_t& r3, uint32_t addr) {
    asm volatile("ldmatrix.sync.aligned.m8n8.x4.trans.shared.b16 {%0,%1,%2,%3}, [%4];"
                 : "=r"(r0), "=r"(r1), "=r"(r2), "=r"(r3) : "r"(addr));
}
// fp16 MMA
__device__ __forceinline__ void mma16816h(float* c, const uint32_t* a, const uint32_t* b) {
    asm volatile("mma.sync.aligned.m16n8k16.row.col.f32.f16.f16.f32 "
                 "{%0,%1,%2,%3}, {%4,%5,%6,%7}, {%8,%9}, {%0,%1,%2,%3};"
                 : "+f"(c[0]), "+f"(c[1]), "+f"(c[2]), "+f"(c[3])
                 : "r"(a[0]), "r"(a[1]), "r"(a[2]), "r"(a[3]),
                   "r"(b[0]), "r"(b[1]));
}

// ---------------------------------------------------------------------------
// truncate: fp32 -> fp16, same layout.
// ---------------------------------------------------------------------------
__global__ void trunc_kernel(const float* __restrict__ in,
                             __half* __restrict__ h, int n4)
{
    int i = blockIdx.x * blockDim.x + threadIdx.x;
    if (i >= n4) return;
    float4 v = ((const float4*)in)[i];
    ((__half2*)h)[2 * i]     = __half2(__float2half(v.x), __float2half(v.y));
    ((__half2*)h)[2 * i + 1] = __half2(__float2half(v.z), __float2half(v.w));
}

// ---------------------------------------------------------------------------
// transpose + truncate: W[K,N] fp32 -> T_h [N,K] fp16
// ---------------------------------------------------------------------------
__global__ void tsplit_kernel(const float* __restrict__ W,
                              __half* __restrict__ Th, int K, int N)
{
    __shared__ float t[32][33];
    int n0 = blockIdx.x * 32, k0 = blockIdx.y * 32;
    int tx = threadIdx.x, ty = threadIdx.y;  // 32 x 8
#pragma unroll
    for (int i = 0; i < 4; i++)
        t[ty + i * 8][tx] = W[(long)(k0 + ty + i * 8) * N + n0 + tx];
    __syncthreads();
#pragma unroll
    for (int i = 0; i < 4; i++) {
        float v = t[tx][ty + i * 8];
        Th[(long)(n0 + ty + i * 8) * K + k0 + tx] = __float2half(v);
    }
}

// ---------------------------------------------------------------------------
// Shared GEMM mainloop: single-product fp16, 128x128x32 CTA tile, 256 threads,
// 8 warps (2Mx4N), 64x32 warp tile, 4-stage cp.async pipeline. (R11 shape.)
// ---------------------------------------------------------------------------
#define ROWB    80
#define TILE_B  (128 * ROWB)             // 10240 B
#define STAGE_B (2 * TILE_B)             // Ah Bh = 20480 B
#define NSTAGE  4
#define GEMM_SMEM_DYN (NSTAGE * STAGE_B) // 81920 B

#define GEMM_MAINLOOP(Ah, Bh, K)                                                \
    extern __shared__ __align__(128) char smem[];                               \
    const uint32_t sbase = smem_to_u32(smem);                                   \
    const int tid  = threadIdx.x;                                               \
    const int lane = tid & 31;                                                  \
    const int wid  = tid >> 5;                                                  \
    const int wm   = wid & 1;                                                   \
    const int wn   = wid >> 1;                                                  \
    const int bm   = blockIdx.y * 128;                                          \
    const int bn   = blockIdx.x * 128;                                          \
    float acc[4][4][4];                                                         \
    _Pragma("unroll")                                                           \
    for (int mi = 0; mi < 4; mi++)                                              \
        _Pragma("unroll")                                                       \
        for (int ni = 0; ni < 4; ni++)                                          \
            _Pragma("unroll")                                                   \
            for (int r = 0; r < 4; r++) acc[mi][ni][r] = 0.f;                   \
    const int row = tid & 127;                                                  \
    const int ch  = tid >> 7;                                                   \
    const __half* gA = Ah + (long)bm * (K);                                     \
    const __half* gB = Bh + (long)bn * (K);                                     \
    const int NS = (K) / 32;                                                    \
    auto load_stage = [&](int s) {                                              \
        const int k0 = s * 32;                                                  \
        const uint32_t buf = sbase + (s % NSTAGE) * STAGE_B;                    \
        _Pragma("unroll")                                                       \
        for (int j = 0; j < 2; j++) {                                           \
            int c = ch + 2 * j;                                                 \
            cp_async16(buf + row * ROWB + c * 16,                               \
                       gA + (long)row * (K) + k0 + c * 8);                      \
            cp_async16(buf + TILE_B + row * ROWB + c * 16,                      \
                       gB + (long)row * (K) + k0 + c * 8);                      \
        }                                                                       \
    };                                                                          \
    load_stage(0);                                                              \
    CP_COMMIT();                                                                \
    load_stage(1);                                                              \
    CP_COMMIT();                                                                \
    load_stage(2);                                                              \
    CP_COMMIT();                                                                \
    const int arow  = wm * 64 + (lane & 15);                                    \
    const int asel  = (lane >> 4) << 3;                                         \
    const int brow  = wn * 32 + (lane & 7) + ((lane >> 4) << 3);                \
    const int bsel  = ((lane >> 3) & 1) << 3;                                   \
    for (int s = 0; s < NS; s++) {                                              \
        if (s + 3 < NS) {                                                       \
            load_stage(s + 3);                                                  \
            CP_COMMIT();                                                        \
            CP_WAIT(3);                                                         \
        } else {                                                                \
            CP_WAIT(0);                                                         \
        }                                                                       \
        __syncthreads();                                                        \
        const uint32_t buf = sbase + (s % NSTAGE) * STAGE_B;                    \
        _Pragma("unroll")                                                       \
        for (int ks = 0; ks < 2; ks++) {                                        \
            uint32_t a[4][4];                                                   \
            uint32_t b[4][2];                                                   \
            const int acol = ks * 16 + asel;                                    \
            const int bcol = ks * 16 + bsel;                                    \
            _Pragma("unroll")                                                   \
            for (int nj = 0; nj < 2; nj++)                                      \
                ldsm_x4(b[nj * 2][0], b[nj * 2][1],                             \
                        b[nj * 2 + 1][0], b[nj * 2 + 1][1],                     \
                        buf + TILE_B + (brow + nj * 16) * ROWB + bcol * 2);     \
            _Pragma("unroll")                                                   \
            for (int mi = 0; mi < 4; mi++)                                      \
                ldsm_x4(a[mi][0], a[mi][1], a[mi][2], a[mi][3],                 \
                        buf + (arow + mi * 16) * ROWB + acol * 2);              \
            _Pragma("unroll")                                                   \
            for (int mi = 0; mi < 4; mi++)                                      \
                _Pragma("unroll")                                               \
                for (int ni = 0; ni < 4; ni++)                                  \
                    mma16816h(acc[mi][ni], a[mi], b[ni]);                       \
        }                                                                       \
        __syncthreads();                                                        \
    }

// ---------------------------------------------------------------------------
// Projection GEMM: fp32 out + bias (final output)
// ---------------------------------------------------------------------------
__global__ void __launch_bounds__(256, 2) gemm_proj(
    const __half* __restrict__ Ah, const __half* __restrict__ Bh,
    const float* __restrict__ bias, float* __restrict__ C, int N, int K)
{
    GEMM_MAINLOOP(Ah, Bh, K)

    const int g  = lane >> 2;
    const int t4 = lane & 3;
#pragma unroll
    for (int mi = 0; mi < 4; mi++) {
#pragma unroll
        for (int ni = 0; ni < 4; ni++) {
            const int col = bn + wn * 32 + ni * 8 + t4 * 2;
            const long r0 = bm + wm * 64 + mi * 16 + g;
            float2 bb = *(const float2*)&bias[col];
            float2 o0 = { acc[mi][ni][0] + bb.x, acc[mi][ni][1] + bb.y };
            float2 o1 = { acc[mi][ni][2] + bb.x, acc[mi][ni][3] + bb.y };
            *(float2*)&C[r0 * N + col] = o0;
            *(float2*)&C[(r0 + 8) * N + col] = o1;
        }
    }
}

// ---------------------------------------------------------------------------
// QKV GEMM: epilogue writes Q(scaled)/K/V fp16 trunc directly to [b,h,s,d].
// ---------------------------------------------------------------------------
__global__ void __launch_bounds__(256, 2) gemm_qkv(
    const __half* __restrict__ Ah, const __half* __restrict__ Bh,
    const float* __restrict__ bias,
    __half* __restrict__ Qh, __half* __restrict__ Kh, __half* __restrict__ Vh,
    int K)
{
    GEMM_MAINLOOP(Ah, Bh, K)

    const int g  = lane >> 2;
    const int t4 = lane & 3;
    const int region = bn >> 10;            // 0=Q 1=K 2=V
    __half* Dh;
    float scale = 1.f;
    if (region == 0) { Dh = Qh; scale = 0.125f; }
    else if (region == 1) { Dh = Kh; }
    else { Dh = Vh; }

#pragma unroll
    for (int mi = 0; mi < 4; mi++) {
#pragma unroll
        for (int ni = 0; ni < 4; ni++) {
            const int colg = bn + wn * 32 + ni * 8 + t4 * 2;
            const int c    = colg & 1023;
            const int h    = c >> 6, d = c & 63;
            const long r0  = bm + wm * 64 + mi * 16 + g;       // = b*S + s
            const int b    = (int)(r0 >> 10);
            const int s    = (int)(r0 & 1023);
            float2 bb = *(const float2*)&bias[colg];
            long o = (((long)b * H_ + h) * S_ + s) * D_ + d;
            *(__half2*)&Dh[o] =
                __half2(__float2half((acc[mi][ni][0] + bb.x) * scale),
                        __float2half((acc[mi][ni][1] + bb.y) * scale));
            *(__half2*)&Dh[o + 8 * D_] =
                __half2(__float2half((acc[mi][ni][2] + bb.x) * scale),
                        __float2half((acc[mi][ni][3] + bb.y) * scale));
        }
    }
}

// ---------------------------------------------------------------------------
// Causal flash-attention: single-product fp16 HMMA; V in [s][d], PV trans-ldsm.
// Epilogue writes fp16 (trunc) directly as proj GEMM input.
// ---------------------------------------------------------------------------
#define ATS 72
#define SST 68

#define Q_H    0
#define K_H    (64 * ATS)
#define V_H    (2 * 64 * ATS)
#define P_H    (3 * 64 * ATS)
#define S_OFF  (4 * 64 * ATS)
#define ATTN2_SMEM (4 * 64 * ATS * 2 + 64 * SST * 4 + 2 * 64 * 4)

__global__ void __launch_bounds__(256, 2) attn_mma(
    const __half* __restrict__ Qh, const __half* __restrict__ Kh,
    const __half* __restrict__ Vh, __half* __restrict__ Oh)
{
    extern __shared__ __align__(128) char asmem[];
    __half* hfs    = (__half*)asmem;
    float* Ss      = (float*)(asmem + S_OFF * 2);
    float* alpha_s = Ss + 64 * SST;
    float* linv_s  = alpha_s + 64;
    const uint32_t sb = smem_to_u32(asmem);

    const int tid  = threadIdx.x;
    const int lane = tid & 31;
    const int wid  = tid >> 5;
    const int wm   = wid & 3;
    const int wn   = wid >> 2;
    const int qt   = blockIdx.x;
    const int h    = blockIdx.y;
    const int b    = blockIdx.z;
    const int q0   = qt * 64;
    const int tx   = tid & 15;
    const int ty   = tid >> 4;

    const long bh = (long)b * H_ + h;

    // ---- Q tile via cp.async (once): 64 rows x 8 chunks = 512
    {
        const __half* qs = Qh + (bh * S_ + q0) * D_;
#pragma unroll
        for (int j = 0; j < 2; j++) {
            int lin = tid + j * 256;
            int r = lin >> 3, c = lin & 7;
            cp_async16(sb + Q_H * 2 + r * (ATS * 2) + c * 16,
                       qs + (long)r * D_ + c * 8);
        }
    }

    float m[4], l[4];
    float oacc[4][4];
#pragma unroll
    for (int i = 0; i < 4; i++) {
        m[i] = -1e30f; l[i] = 0.f;
#pragma unroll
        for (int j = 0; j < 4; j++) oacc[i][j] = 0.f;
    }

    const int arow = wm * 16 + (lane & 15);
    const int asel = (lane >> 4) << 3;
    const int brow = wn * 32 + (lane & 7) + ((lane >> 4) << 3);
    const int bsel = ((lane >> 3) & 1) << 3;
    const int vrow = ((lane >> 3) & 1) * 8 + (lane & 7);
    const int vcol = wn * 32 + ((lane >> 4) << 3);
    const int g    = lane >> 2;
    const int t4   = lane & 3;

    for (int kt = 0; kt <= qt; kt++) {
        __syncthreads();

        // ---- K + V tiles via cp.async: 2 tiles x 512 chunks
        {
            const __half* ks = Kh + (bh * S_ + kt * 64) * D_;
            const __half* vs = Vh + (bh * S_ + kt * 64) * D_;
#pragma unroll
            for (int j = 0; j < 2; j++) {
                int lin = tid + j * 256;
                int r = lin >> 3, c = lin & 7;
                cp_async16(sb + K_H * 2 + r * (ATS * 2) + c * 16,
                           ks + (long)r * D_ + c * 8);
                cp_async16(sb + V_H * 2 + r * (ATS * 2) + c * 16,
                           vs + (long)r * D_ + c * 8);
            }
        }
        CP_COMMIT();
        CP_WAIT(0);
        __syncthreads();

        // ---- S = Q @ K^T (single product fp16) ----
        float sacc[4][4];
#pragma unroll
        for (int ni = 0; ni < 4; ni++)
#pragma unroll
            for (int r = 0; r < 4; r++) sacc[ni][r] = 0.f;

#pragma unroll
        for (int ks = 0; ks < 4; ks++) {
            const int acol = ks * 16 + asel;
            const int bcol = ks * 16 + bsel;
            uint32_t a[4], bq[4][2];
            ldsm_x4(a[0], a[1], a[2], a[3],
                    sb + (Q_H + arow * ATS + acol) * 2);
#pragma unroll
            for (int nj = 0; nj < 2; nj++)
                ldsm_x4(bq[nj * 2][0], bq[nj * 2][1], bq[nj * 2 + 1][0], bq[nj * 2 + 1][1],
                        sb + (K_H + (brow + nj * 16) * ATS + bcol) * 2);
#pragma unroll
            for (int ni = 0; ni < 4; ni++)
                mma16816h(sacc[ni], a, bq[ni]);
        }
#pragma unroll
        for (int ni = 0; ni < 4; ni++) {
            const int col = wn * 32 + ni * 8 + t4 * 2;
            *(float2*)&Ss[(wm * 16 + g) * SST + col]     = make_float2(sacc[ni][0], sacc[ni][1]);
            *(float2*)&Ss[(wm * 16 + g + 8) * SST + col] = make_float2(sacc[ni][2], sacc[ni][3]);
        }
        __syncthreads();

        // ---- scalar online softmax; emit P fp16 + alpha ----
        float s[4][4];
#pragma unroll
        for (int i = 0; i < 4; i++)
#pragma unroll
            for (int j = 0; j < 4; j++)
                s[i][j] = Ss[(ty * 4 + i) * SST + tx * 4 + j];

        if (kt == qt) {
#pragma unroll
            for (int i = 0; i < 4; i++)
#pragma unroll
                for (int j = 0; j < 4; j++)
                    if (tx * 4 + j > ty * 4 + i) s[i][j] = -1e9f;
        }

#pragma unroll
        for (int i = 0; i < 4; i++) {
            float mx = fmaxf(fmaxf(s[i][0], s[i][1]), fmaxf(s[i][2], s[i][3]));
#pragma unroll
            for (int off = 8; off > 0; off >>= 1)
                mx = fmaxf(mx, __shfl_xor_sync(0xffffffffu, mx, off));
            float mnew = fmaxf(m[i], mx);
            float alpha = __expf(m[i] - mnew);
            m[i] = mnew;
            float rs = 0.f;
#pragma unroll
            for (int j = 0; j < 4; j++) {
                s[i][j] = __expf(s[i][j] - mnew);
                rs += s[i][j];
            }
#pragma unroll
            for (int off = 8; off > 0; off >>= 1)
                rs += __shfl_xor_sync(0xffffffffu, rs, off);
            l[i] = l[i] * alpha + rs;
            if (tx == 0) alpha_s[ty * 4 + i] = alpha;
            const int pr = (ty * 4 + i) * ATS + tx * 4;
            *(__half2*)&hfs[P_H + pr] =
                __half2(__float2half(s[i][0]), __float2half(s[i][1]));
            *(__half2*)&hfs[P_H + pr + 2] =
                __half2(__float2half(s[i][2]), __float2half(s[i][3]));
        }
        __syncthreads();

        // ---- O = O*alpha + P @ V (single product fp16) ----
        const float al0 = alpha_s[wm * 16 + g];
        const float al1 = alpha_s[wm * 16 + g + 8];
#pragma unroll
        for (int ni = 0; ni < 4; ni++) {
            oacc[ni][0] *= al0; oacc[ni][1] *= al0;
            oacc[ni][2] *= al1; oacc[ni][3] *= al1;
        }
#pragma unroll
        for (int ks = 0; ks < 4; ks++) {
            const int acol = ks * 16 + asel;
            uint32_t a[4], bv[4][2];
            ldsm_x4(a[0], a[1], a[2], a[3],
                    sb + (P_H + arow * ATS + acol) * 2);
#pragma unroll
            for (int nj = 0; nj < 2; nj++) {
                const uint32_t vaddr = (ks * 16 + vrow) * ATS + vcol + nj * 16;
                ldsm_x4t(bv[nj * 2][0], bv[nj * 2][1], bv[nj * 2 + 1][0], bv[nj * 2 + 1][1],
                         sb + (V_H + vaddr) * 2);
            }
#pragma unroll
            for (int ni = 0; ni < 4; ni++)
                mma16816h(oacc[ni], a, bv[ni]);
        }
    }

    // ---- epilogue
#pragma unroll
    for (int i = 0; i < 4; i++)
        if (tx == 0) linv_s[ty * 4 + i] = 1.f / l[i];
    __syncthreads();

    const float li0 = linv_s[wm * 16 + g];
    const float li1 = linv_s[wm * 16 + g + 8];
#pragma unroll
    for (int ni = 0; ni < 4; ni++) {
        const int col = h * D_ + wn * 32 + ni * 8 + t4 * 2;
        const long r0 = (long)b * S_ + q0 + wm * 16 + g;
        *(__half2*)&Oh[r0 * NX_ + col] =
            __half2(__float2half(oacc[ni][0] * li0), __float2half(oacc[ni][1] * li0));
        *(__half2*)&Oh[(r0 + 8) * NX_ + col] =
            __half2(__float2half(oacc[ni][2] * li1), __float2half(oacc[ni][3] * li1));
    }
}

// ---------------------------------------------------------------------------
extern "C" void kernel_launch(void* const* d_in, const int* in_sizes, int n_in,
                              void* d_out, int out_size)
{
    const float* x      = (const float*)d_in[0];
    const float* w_attn = (const float*)d_in[1];
    const float* b_attn = (const float*)d_in[2];
    const float* w_proj = (const float*)d_in[3];
    const float* b_proj = (const float*)d_in[4];
    float* out = (float*)d_out;

    __half *xh, *ah, *wqh, *wph, *qh, *kh, *vh;
    cudaGetSymbolAddress((void**)&xh, g_xh);
    cudaGetSymbolAddress((void**)&ah, g_ah);
    cudaGetSymbolAddress((void**)&wqh, g_wqkv_h);
    cudaGetSymbolAddress((void**)&wph, g_wproj_h);
    cudaGetSymbolAddress((void**)&qh, g_qh);
    cudaGetSymbolAddress((void**)&kh, g_kh);
    cudaGetSymbolAddress((void**)&vh, g_vh);

    cudaFuncSetAttribute(attn_mma,
                         cudaFuncAttributeMaxDynamicSharedMemorySize, ATTN2_SMEM);
    cudaFuncSetAttribute(gemm_qkv,
                         cudaFuncAttributeMaxDynamicSharedMemorySize, GEMM_SMEM_DYN);
    cudaFuncSetAttribute(gemm_proj,
                         cudaFuncAttributeMaxDynamicSharedMemorySize, GEMM_SMEM_DYN);

    const int M = B_ * S_;  // 8192

    // truncate x to fp16
    {
        int n4 = M * NX_ / 4;
        trunc_kernel<<<(n4 + 255) / 256, 256>>>(x, xh, n4);
    }
    // transpose+truncate weights (fp16)
    tsplit_kernel<<<dim3(3 * NX_ / 32, NX_ / 32), dim3(32, 8)>>>(w_attn, wqh, NX_, 3 * NX_);
    tsplit_kernel<<<dim3(NX_ / 32, NX_ / 32), dim3(32, 8)>>>(w_proj, wph, NX_, NX_);

    // QKV GEMM (single-product fp16) with fused fp16 epilogue
    gemm_qkv<<<dim3(3 * NX_ / 128, M / 128), 256, GEMM_SMEM_DYN>>>(
        xh, wqh, b_attn, qh, kh, vh, NX_);

    // attention (single-product fp16 HMMA) -> fp16 trunc
    attn_mma<<<dim3(S_ / 64, H_, B_), 256, ATTN2_SMEM>>>(qh, kh, vh, ah);

    // projection GEMM (single-product fp16) -> final fp32 output
    gemm_proj<<<dim3(NX_ / 128, M / 128), 256, GEMM_SMEM_DYN>>>(
        ah, wph, b_proj, out, NX_, NX_);
}

// round 13
// speedup vs baseline: 2.5504x; 1.5997x over previous
#include <cuda_runtime.h>
#include <cuda_bf16.h>
#include <cuda_fp16.h>
#include <cstdint>

#define B_  8
#define S_  1024
#define NX_ 1024
#define H_  16
#define D_  64

// ---------------- scratch (__device__ globals; no allocation) ----------------
__device__ __half g_xh[B_ * S_ * NX_];               // x, fp16 trunc
__device__ __half g_ah[B_ * S_ * NX_];               // attention out, fp16 trunc
__device__ __half g_wqkv_h[3 * NX_ * NX_];           // [N=3072, K=1024] fp16 trunc
__device__ __half g_wproj_h[NX_ * NX_];              // [N=1024, K=1024]
__device__ __half g_qh[B_ * H_ * S_ * D_];           // [b,h,s,d], pre-scaled 0.125
__device__ __half g_kh[B_ * H_ * S_ * D_];
__device__ __half g_vh[B_ * H_ * S_ * D_];

// ---------------- PTX helpers ----------------
__device__ __forceinline__ uint32_t smem_to_u32(const void* p) {
    uint32_t a;
    asm("{ .reg .u64 t; cvta.to.shared.u64 t, %1; cvt.u32.u64 %0, t; }"
        : "=r"(a) : "l"(p));
    return a;
}
__device__ __forceinline__ void cp_async16(uint32_t dst, const void* src) {
    asm volatile("cp.async.cg.shared.global [%0], [%1], 16;"
                 :: "r"(dst), "l"(src) : "memory");
}
#define CP_COMMIT() asm volatile("cp.async.commit_group;" ::: "memory")
#define CP_WAIT(n)  asm volatile("cp.async.wait_group %0;" :: "n"(n) : "memory")

__device__ __forceinline__ void ldsm_x4(uint32_t& r0, uint32_t& r1,
                                        uint32_t& r2, uint32_t& r3, uint32_t addr) {
    asm volatile("ldmatrix.sync.aligned.m8n8.x4.shared.b16 {%0,%1,%2,%3}, [%4];"
                 : "=r"(r0), "=r"(r1), "=r"(r2), "=r"(r3) : "r"(addr));
}
__device__ __forceinline__ void ldsm_x4t(uint32_t& r0, uint32_t& r1,
                                         uint32_t& r2, uint32_t& r3, uint32_t addr) {
    asm volatile("ldmatrix.sync.aligned.m8n8.x4.trans.shared.b16 {%0,%1,%2,%3}, [%4];"
                 : "=r"(r0), "=r"(r1), "=r"(r2), "=r"(r3) : "r"(addr));
}
__device__ __forceinline__ void mma16816h(float* c, const uint32_t* a, const uint32_t* b) {
    asm volatile("mma.sync.aligned.m16n8k16.row.col.f32.f16.f16.f32 "
                 "{%0,%1,%2,%3}, {%4,%5,%6,%7}, {%8,%9}, {%0,%1,%2,%3};"
                 : "+f"(c[0]), "+f"(c[1]), "+f"(c[2]), "+f"(c[3])
                 : "r"(a[0]), "r"(a[1]), "r"(a[2]), "r"(a[3]),
                   "r"(b[0]), "r"(b[1]));
}
__device__ __forceinline__ uint32_t packh2(float x, float y) {
    __half2 h = __halves2half2(__float2half(x), __float2half(y));
    return *(uint32_t*)&h;
}

// ---------------------------------------------------------------------------
// truncate: fp32 -> fp16, same layout.
// ---------------------------------------------------------------------------
__global__ void trunc_kernel(const float* __restrict__ in,
                             __half* __restrict__ h, int n4)
{
    int i = blockIdx.x * blockDim.x + threadIdx.x;
    if (i >= n4) return;
    float4 v = ((const float4*)in)[i];
    ((__half2*)h)[2 * i]     = __half2(__float2half(v.x), __float2half(v.y));
    ((__half2*)h)[2 * i + 1] = __half2(__float2half(v.z), __float2half(v.w));
}

// ---------------------------------------------------------------------------
// transpose + truncate: W[K,N] fp32 -> T_h [N,K] fp16
// ---------------------------------------------------------------------------
__global__ void tsplit_kernel(const float* __restrict__ W,
                              __half* __restrict__ Th, int K, int N)
{
    __shared__ float t[32][33];
    int n0 = blockIdx.x * 32, k0 = blockIdx.y * 32;
    int tx = threadIdx.x, ty = threadIdx.y;  // 32 x 8
#pragma unroll
    for (int i = 0; i < 4; i++)
        t[ty + i * 8][tx] = W[(long)(k0 + ty + i * 8) * N + n0 + tx];
    __syncthreads();
#pragma unroll
    for (int i = 0; i < 4; i++) {
        float v = t[tx][ty + i * 8];
        Th[(long)(n0 + ty + i * 8) * K + k0 + tx] = __float2half(v);
    }
}

// ---------------------------------------------------------------------------
// GEMM mainloop: single-product fp16, 128x128x64 CTA tile, 256 threads,
// 8 warps (2Mx4N), 2-stage cp.async pipeline, ONE sync per stage.
// ---------------------------------------------------------------------------
#define ROWB    144                      // 128B row + 16B pad (stride 9 x 16B)
#define TILE_B  (128 * ROWB)             // 18432 B
#define STAGE_B (2 * TILE_B)             // 36864 B
#define GEMM_SMEM_DYN (2 * STAGE_B)      // 73728 B -> 2 CTAs/SM

#define GEMM_MAINLOOP(Ah, Bh, K)                                                \
    extern __shared__ __align__(128) char smem[];                               \
    const uint32_t sbase = smem_to_u32(smem);                                   \
    const int tid  = threadIdx.x;                                               \
    const int lane = tid & 31;                                                  \
    const int wid  = tid >> 5;                                                  \
    const int wm   = wid & 1;                                                   \
    const int wn   = wid >> 1;                                                  \
    const int bm   = blockIdx.y * 128;                                          \
    const int bn   = blockIdx.x * 128;                                          \
    float acc[4][4][4];                                                         \
    _Pragma("unroll")                                                           \
    for (int mi = 0; mi < 4; mi++)                                              \
        _Pragma("unroll")                                                       \
        for (int ni = 0; ni < 4; ni++)                                          \
            _Pragma("unroll")                                                   \
            for (int r = 0; r < 4; r++) acc[mi][ni][r] = 0.f;                   \
    const __half* gA = Ah + (long)bm * (K);                                     \
    const __half* gB = Bh + (long)bn * (K);                                     \
    const int NS = (K) / 64;                                                    \
    auto load_stage = [&](int s) {                                              \
        const int k0 = s * 64;                                                  \
        const uint32_t buf = sbase + (s & 1) * STAGE_B;                         \
        _Pragma("unroll")                                                       \
        for (int p = 0; p < 4; p++) {                                           \
            int lin = tid + p * 256;                                            \
            int r = lin >> 3, c = lin & 7;                                      \
            cp_async16(buf + r * ROWB + c * 16,                                 \
                       gA + (long)r * (K) + k0 + c * 8);                        \
            cp_async16(buf + TILE_B + r * ROWB + c * 16,                        \
                       gB + (long)r * (K) + k0 + c * 8);                        \
        }                                                                       \
    };                                                                          \
    load_stage(0);                                                              \
    CP_COMMIT();                                                                \
    const int arow  = wm * 64 + (lane & 15);                                    \
    const int asel  = (lane >> 4) << 3;                                         \
    const int brow  = wn * 32 + (lane & 7) + ((lane >> 4) << 3);                \
    const int bsel  = ((lane >> 3) & 1) << 3;                                   \
    for (int s = 0; s < NS; s++) {                                              \
        CP_WAIT(0);                                                             \
        __syncthreads();                                                        \
        if (s + 1 < NS) {                                                       \
            load_stage(s + 1);                                                  \
            CP_COMMIT();                                                        \
        }                                                                       \
        const uint32_t buf = sbase + (s & 1) * STAGE_B;                         \
        _Pragma("unroll")                                                       \
        for (int ks = 0; ks < 4; ks++) {                                        \
            uint32_t a[4][4];                                                   \
            uint32_t b[4][2];                                                   \
            const int acol = ks * 16 + asel;                                    \
            const int bcol = ks * 16 + bsel;                                    \
            _Pragma("unroll")                                                   \
            for (int nj = 0; nj < 2; nj++)                                      \
                ldsm_x4(b[nj * 2][0], b[nj * 2][1],                             \
                        b[nj * 2 + 1][0], b[nj * 2 + 1][1],                     \
                        buf + TILE_B + (brow + nj * 16) * ROWB + bcol * 2);     \
            _Pragma("unroll")                                                   \
            for (int mi = 0; mi < 4; mi++)                                      \
                ldsm_x4(a[mi][0], a[mi][1], a[mi][2], a[mi][3],                 \
                        buf + (arow + mi * 16) * ROWB + acol * 2);              \
            _Pragma("unroll")                                                   \
            for (int mi = 0; mi < 4; mi++)                                      \
                _Pragma("unroll")                                               \
                for (int ni = 0; ni < 4; ni++)                                  \
                    mma16816h(acc[mi][ni], a[mi], b[ni]);                       \
        }                                                                       \
    }

// ---------------------------------------------------------------------------
// Projection GEMM: fp32 out + bias (final output)
// ---------------------------------------------------------------------------
__global__ void __launch_bounds__(256, 2) gemm_proj(
    const __half* __restrict__ Ah, const __half* __restrict__ Bh,
    const float* __restrict__ bias, float* __restrict__ C, int N, int K)
{
    GEMM_MAINLOOP(Ah, Bh, K)

    const int g  = lane >> 2;
    const int t4 = lane & 3;
#pragma unroll
    for (int mi = 0; mi < 4; mi++) {
#pragma unroll
        for (int ni = 0; ni < 4; ni++) {
            const int col = bn + wn * 32 + ni * 8 + t4 * 2;
            const long r0 = bm + wm * 64 + mi * 16 + g;
            float2 bb = *(const float2*)&bias[col];
            float2 o0 = { acc[mi][ni][0] + bb.x, acc[mi][ni][1] + bb.y };
            float2 o1 = { acc[mi][ni][2] + bb.x, acc[mi][ni][3] + bb.y };
            *(float2*)&C[r0 * N + col] = o0;
            *(float2*)&C[(r0 + 8) * N + col] = o1;
        }
    }
}

// ---------------------------------------------------------------------------
// QKV GEMM: epilogue writes Q(scaled)/K/V fp16 trunc directly to [b,h,s,d].
// ---------------------------------------------------------------------------
__global__ void __launch_bounds__(256, 2) gemm_qkv(
    const __half* __restrict__ Ah, const __half* __restrict__ Bh,
    const float* __restrict__ bias,
    __half* __restrict__ Qh, __half* __restrict__ Kh, __half* __restrict__ Vh,
    int K)
{
    GEMM_MAINLOOP(Ah, Bh, K)

    const int g  = lane >> 2;
    const int t4 = lane & 3;
    const int region = bn >> 10;            // 0=Q 1=K 2=V
    __half* Dh;
    float scale = 1.f;
    if (region == 0) { Dh = Qh; scale = 0.125f; }
    else if (region == 1) { Dh = Kh; }
    else { Dh = Vh; }

#pragma unroll
    for (int mi = 0; mi < 4; mi++) {
#pragma unroll
        for (int ni = 0; ni < 4; ni++) {
            const int colg = bn + wn * 32 + ni * 8 + t4 * 2;
            const int c    = colg & 1023;
            const int h    = c >> 6, d = c & 63;
            const long r0  = bm + wm * 64 + mi * 16 + g;       // = b*S + s
            const int b    = (int)(r0 >> 10);
            const int s    = (int)(r0 & 1023);
            float2 bb = *(const float2*)&bias[colg];
            long o = (((long)b * H_ + h) * S_ + s) * D_ + d;
            *(__half2*)&Dh[o] =
                __half2(__float2half((acc[mi][ni][0] + bb.x) * scale),
                        __float2half((acc[mi][ni][1] + bb.y) * scale));
            *(__half2*)&Dh[o + 8 * D_] =
                __half2(__float2half((acc[mi][ni][2] + bb.x) * scale),
                        __float2half((acc[mi][ni][3] + bb.y) * scale));
        }
    }
}

// ---------------------------------------------------------------------------
// Causal flash-attention, register-resident softmax (FA2-style).
// 64q x 64k tiles; 8 warps: wm in {0..3} (16 q-rows), wn in {0,1} (32 k-cols).
// S stays in C-fragments; P = A-fragments of PV directly. Partial O per wn,
// combined once in epilogue.
// ---------------------------------------------------------------------------
#define ATS 72                               // halfs per smem tile row (144 B)
#define Q_H 0
#define K_H (64 * ATS)
#define V_H (128 * ATS)
#define OS_OFF   (3 * 64 * ATS * 2)          // bytes; fp32 Os[64][68]
#define OS_STR   68
#define MB_OFF   (OS_OFF + 64 * OS_STR * 4)  // fp32 mbuf[2][64]
#define LB_OFF   (MB_OFF + 2 * 64 * 4)       // fp32 lbuf[2][64]
#define ATTN2_SMEM (LB_OFF + 2 * 64 * 4)

__global__ void __launch_bounds__(256, 2) attn_mma(
    const __half* __restrict__ Qh, const __half* __restrict__ Kh,
    const __half* __restrict__ Vh, __half* __restrict__ Oh)
{
    extern __shared__ __align__(128) char asmem[];
    const uint32_t sb = smem_to_u32(asmem);
    float* Os   = (float*)(asmem + OS_OFF);
    float* mbuf = (float*)(asmem + MB_OFF);
    float* lbuf = (float*)(asmem + LB_OFF);

    const int tid  = threadIdx.x;
    const int lane = tid & 31;
    const int wid  = tid >> 5;
    const int wm   = wid & 3;            // 4 warps along q rows
    const int wn   = wid >> 2;           // 2 warps along k cols
    const int qt   = blockIdx.x;
    const int h    = blockIdx.y;
    const int b    = blockIdx.z;
    const int q0   = qt * 64;
    const long bh  = (long)b * H_ + h;

    const int g    = lane >> 2;
    const int t4   = lane & 3;
    const int row0 = wm * 16 + g;
    const int row1 = row0 + 8;

    // ---- Q tile (once)
    {
        const __half* qs = Qh + (bh * S_ + q0) * D_;
#pragma unroll
        for (int j = 0; j < 2; j++) {
            int lin = tid + j * 256;
            int r = lin >> 3, c = lin & 7;
            cp_async16(sb + (Q_H + r * ATS) * 2 + c * 16, qs + (long)r * D_ + c * 8);
        }
        CP_COMMIT();
    }

    float m2[2] = { -1e30f, -1e30f }, l2[2] = { 0.f, 0.f };
    float oacc[8][4];
#pragma unroll
    for (int nt = 0; nt < 8; nt++)
#pragma unroll
        for (int r = 0; r < 4; r++) oacc[nt][r] = 0.f;

    const int arow = wm * 16 + (lane & 15);
    const int asel = (lane >> 4) << 3;
    const int brow = wn * 32 + (lane & 7) + ((lane >> 4) << 3);
    const int bsel = ((lane >> 3) & 1) << 3;
    const int vrow = ((lane >> 3) & 1) * 8 + (lane & 7);
    const int vcol = (lane >> 4) << 3;

    for (int kt = 0; kt <= qt; kt++) {
        __syncthreads();   // K/V + mbuf/lbuf reuse guard

        {
            const __half* ks = Kh + (bh * S_ + kt * 64) * D_;
            const __half* vs = Vh + (bh * S_ + kt * 64) * D_;
#pragma unroll
            for (int j = 0; j < 2; j++) {
                int lin = tid + j * 256;
                int r = lin >> 3, c = lin & 7;
                cp_async16(sb + (K_H + r * ATS) * 2 + c * 16, ks + (long)r * D_ + c * 8);
                cp_async16(sb + (V_H + r * ATS) * 2 + c * 16, vs + (long)r * D_ + c * 8);
            }
        }
        CP_COMMIT();
        CP_WAIT(0);
        __syncthreads();

        // ---- S = Q @ K^T
        float s[4][4];
#pragma unroll
        for (int ni = 0; ni < 4; ni++)
#pragma unroll
            for (int r = 0; r < 4; r++) s[ni][r] = 0.f;

#pragma unroll
        for (int ks = 0; ks < 4; ks++) {
            const int acol = ks * 16 + asel;
            const int bcol = ks * 16 + bsel;
            uint32_t a[4], bq[4][2];
            ldsm_x4(a[0], a[1], a[2], a[3], sb + (Q_H + arow * ATS + acol) * 2);
#pragma unroll
            for (int nj = 0; nj < 2; nj++)
                ldsm_x4(bq[nj * 2][0], bq[nj * 2][1], bq[nj * 2 + 1][0], bq[nj * 2 + 1][1],
                        sb + (K_H + (brow + nj * 16) * ATS + bcol) * 2);
#pragma unroll
            for (int ni = 0; ni < 4; ni++)
                mma16816h(s[ni], a, bq[ni]);
        }

        // ---- causal mask (diagonal tile)
        if (kt == qt) {
#pragma unroll
            for (int ni = 0; ni < 4; ni++) {
                const int col = wn * 32 + ni * 8 + t4 * 2;
                if (col > row0)     s[ni][0] = -1e9f;
                if (col + 1 > row0) s[ni][1] = -1e9f;
                if (col > row1)     s[ni][2] = -1e9f;
                if (col + 1 > row1) s[ni][3] = -1e9f;
            }
        }

        // ---- row max: quad shfl + cross-wn smem
        float mx0 = -1e30f, mx1 = -1e30f;
#pragma unroll
        for (int ni = 0; ni < 4; ni++) {
            mx0 = fmaxf(mx0, fmaxf(s[ni][0], s[ni][1]));
            mx1 = fmaxf(mx1, fmaxf(s[ni][2], s[ni][3]));
        }
        mx0 = fmaxf(mx0, __shfl_xor_sync(0xffffffffu, mx0, 1));
        mx0 = fmaxf(mx0, __shfl_xor_sync(0xffffffffu, mx0, 2));
        mx1 = fmaxf(mx1, __shfl_xor_sync(0xffffffffu, mx1, 1));
        mx1 = fmaxf(mx1, __shfl_xor_sync(0xffffffffu, mx1, 2));
        if (t4 == 0) {
            mbuf[wn * 64 + row0] = mx0;
            mbuf[wn * 64 + row1] = mx1;
        }
        __syncthreads();
        const float gm0 = fmaxf(mbuf[row0], mbuf[64 + row0]);
        const float gm1 = fmaxf(mbuf[row1], mbuf[64 + row1]);
        const float mn0 = fmaxf(m2[0], gm0), mn1 = fmaxf(m2[1], gm1);
        const float alpha0 = __expf(m2[0] - mn0), alpha1 = __expf(m2[1] - mn1);
        m2[0] = mn0; m2[1] = mn1;

        // ---- exp + row sum
        float rs0 = 0.f, rs1 = 0.f;
#pragma unroll
        for (int ni = 0; ni < 4; ni++) {
            s[ni][0] = __expf(s[ni][0] - mn0);
            s[ni][1] = __expf(s[ni][1] - mn0);
            s[ni][2] = __expf(s[ni][2] - mn1);
            s[ni][3] = __expf(s[ni][3] - mn1);
            rs0 += s[ni][0] + s[ni][1];
            rs1 += s[ni][2] + s[ni][3];
        }
        rs0 += __shfl_xor_sync(0xffffffffu, rs0, 1);
        rs0 += __shfl_xor_sync(0xffffffffu, rs0, 2);
        rs1 += __shfl_xor_sync(0xffffffffu, rs1, 1);
        rs1 += __shfl_xor_sync(0xffffffffu, rs1, 2);
        if (t4 == 0) {
            lbuf[wn * 64 + row0] = rs0;
            lbuf[wn * 64 + row1] = rs1;
        }
        __syncthreads();
        l2[0] = l2[0] * alpha0 + lbuf[row0] + lbuf[64 + row0];
        l2[1] = l2[1] * alpha1 + lbuf[row1] + lbuf[64 + row1];

        // ---- P as PV A-fragments, straight from C-regs (no smem)
        uint32_t pa[2][4];
#pragma unroll
        for (int j = 0; j < 2; j++) {
            pa[j][0] = packh2(s[2 * j][0],     s[2 * j][1]);
            pa[j][1] = packh2(s[2 * j][2],     s[2 * j][3]);
            pa[j][2] = packh2(s[2 * j + 1][0], s[2 * j + 1][1]);
            pa[j][3] = packh2(s[2 * j + 1][2], s[2 * j + 1][3]);
        }

        // ---- O = O*alpha + P @ V (warp's 32 k-cols, all 64 d)
#pragma unroll
        for (int nt = 0; nt < 8; nt++) {
            oacc[nt][0] *= alpha0; oacc[nt][1] *= alpha0;
            oacc[nt][2] *= alpha1; oacc[nt][3] *= alpha1;
        }
#pragma unroll
        for (int j = 0; j < 2; j++) {
            const int kb = wn * 32 + j * 16;
            uint32_t bv[8][2];
#pragma unroll
            for (int nj = 0; nj < 4; nj++)
                ldsm_x4t(bv[nj * 2][0], bv[nj * 2][1], bv[nj * 2 + 1][0], bv[nj * 2 + 1][1],
                         sb + (V_H + (kb + vrow) * ATS + vcol + nj * 16) * 2);
#pragma unroll
            for (int nt = 0; nt < 8; nt++)
                mma16816h(oacc[nt], pa[j], bv[nt]);
        }
    }

    // ---- epilogue: combine wn partials, normalize, write fp16
    if (wn == 1) {
#pragma unroll
        for (int nt = 0; nt < 8; nt++) {
            const int c = nt * 8 + t4 * 2;
            Os[row0 * OS_STR + c]     = oacc[nt][0];
            Os[row0 * OS_STR + c + 1] = oacc[nt][1];
            Os[row1 * OS_STR + c]     = oacc[nt][2];
            Os[row1 * OS_STR + c + 1] = oacc[nt][3];
        }
    }
    __syncthreads();
    if (wn == 0) {
        const float inv0 = 1.f / l2[0], inv1 = 1.f / l2[1];
        const long r0 = (long)b * S_ + q0 + row0;
#pragma unroll
        for (int nt = 0; nt < 8; nt++) {
            const int c = nt * 8 + t4 * 2;
            const int col = h * D_ + c;
            float f0 = (oacc[nt][0] + Os[row0 * OS_STR + c])     * inv0;
            float f1 = (oacc[nt][1] + Os[row0 * OS_STR + c + 1]) * inv0;
            float f2 = (oacc[nt][2] + Os[row1 * OS_STR + c])     * inv1;
            float f3 = (oacc[nt][3] + Os[row1 * OS_STR + c + 1]) * inv1;
            *(__half2*)&Oh[r0 * NX_ + col] =
                __half2(__float2half(f0), __float2half(f1));
            *(__half2*)&Oh[(r0 + 8) * NX_ + col] =
                __half2(__float2half(f2), __float2half(f3));
        }
    }
}

// ---------------------------------------------------------------------------
extern "C" void kernel_launch(void* const* d_in, const int* in_sizes, int n_in,
                              void* d_out, int out_size)
{
    const float* x      = (const float*)d_in[0];
    const float* w_attn = (const float*)d_in[1];
    const float* b_attn = (const float*)d_in[2];
    const float* w_proj = (const float*)d_in[3];
    const float* b_proj = (const float*)d_in[4];
    float* out = (float*)d_out;

    __half *xh, *ah, *wqh, *wph, *qh, *kh, *vh;
    cudaGetSymbolAddress((void**)&xh, g_xh);
    cudaGetSymbolAddress((void**)&ah, g_ah);
    cudaGetSymbolAddress((void**)&wqh, g_wqkv_h);
    cudaGetSymbolAddress((void**)&wph, g_wproj_h);
    cudaGetSymbolAddress((void**)&qh, g_qh);
    cudaGetSymbolAddress((void**)&kh, g_kh);
    cudaGetSymbolAddress((void**)&vh, g_vh);

    cudaFuncSetAttribute(attn_mma,
                         cudaFuncAttributeMaxDynamicSharedMemorySize, ATTN2_SMEM);
    cudaFuncSetAttribute(gemm_qkv,
                         cudaFuncAttributeMaxDynamicSharedMemorySize, GEMM_SMEM_DYN);
    cudaFuncSetAttribute(gemm_proj,
                         cudaFuncAttributeMaxDynamicSharedMemorySize, GEMM_SMEM_DYN);

    const int M = B_ * S_;  // 8192

    // truncate x to fp16
    {
        int n4 = M * NX_ / 4;
        trunc_kernel<<<(n4 + 255) / 256, 256>>>(x, xh, n4);
    }
    // transpose+truncate weights (fp16)
    tsplit_kernel<<<dim3(3 * NX_ / 32, NX_ / 32), dim3(32, 8)>>>(w_attn, wqh, NX_, 3 * NX_);
    tsplit_kernel<<<dim3(NX_ / 32, NX_ / 32), dim3(32, 8)>>>(w_proj, wph, NX_, NX_);

    // QKV GEMM (single-product fp16) with fused fp16 epilogue
    gemm_qkv<<<dim3(3 * NX_ / 128, M / 128), 256, GEMM_SMEM_DYN>>>(
        xh, wqh, b_attn, qh, kh, vh, NX_);

    // attention (register-softmax fp16 HMMA) -> fp16 trunc
    attn_mma<<<dim3(S_ / 64, H_, B_), 256, ATTN2_SMEM>>>(qh, kh, vh, ah);

    // projection GEMM (single-product fp16) -> final fp32 output
    gemm_proj<<<dim3(NX_ / 128, M / 128), 256, GEMM_SMEM_DYN>>>(
        ah, wph, b_proj, out, NX_, NX_);
}

// round 14
// speedup vs baseline: 2.7394x; 1.0741x over previous
#include <cuda_runtime.h>
#include <cuda_bf16.h>
#include <cuda_fp16.h>
#include <cstdint>

#define B_  8
#define S_  1024
#define NX_ 1024
#define H_  16
#define D_  64

// ---------------- scratch (__device__ globals; no allocation) ----------------
__device__ __half g_xh[B_ * S_ * NX_];               // x, fp16 trunc
__device__ __half g_ah[B_ * S_ * NX_];               // attention out, fp16 trunc
__device__ __half g_wqkv_h[3 * NX_ * NX_];           // [N=3072, K=1024] fp16 trunc
__device__ __half g_wproj_h[NX_ * NX_];              // [N=1024, K=1024]
__device__ __half g_qh[B_ * H_ * S_ * D_];           // [b,h,s,d], pre-scaled 0.125
__device__ __half g_kh[B_ * H_ * S_ * D_];
__device__ __half g_vh[B_ * H_ * S_ * D_];

// ---------------- PTX helpers ----------------
__device__ __forceinline__ uint32_t smem_to_u32(const void* p) {
    uint32_t a;
    asm("{ .reg .u64 t; cvta.to.shared.u64 t, %1; cvt.u32.u64 %0, t; }"
        : "=r"(a) : "l"(p));
    return a;
}
__device__ __forceinline__ void cp_async16(uint32_t dst, const void* src) {
    asm volatile("cp.async.cg.shared.global [%0], [%1], 16;"
                 :: "r"(dst), "l"(src) : "memory");
}
#define CP_COMMIT() asm volatile("cp.async.commit_group;" ::: "memory")
#define CP_WAIT(n)  asm volatile("cp.async.wait_group %0;" :: "n"(n) : "memory")

__device__ __forceinline__ void ldsm_x4(uint32_t& r0, uint32_t& r1,
                                        uint32_t& r2, uint32_t& r3, uint32_t addr) {
    asm volatile("ldmatrix.sync.aligned.m8n8.x4.shared.b16 {%0,%1,%2,%3}, [%4];"
                 : "=r"(r0), "=r"(r1), "=r"(r2), "=r"(r3) : "r"(addr));
}
__device__ __forceinline__ void ldsm_x4t(uint32_t& r0, uint32_t& r1,
                                         uint32_t& r2, uint32_t& r3, uint32_t addr) {
    asm volatile("ldmatrix.sync.aligned.m8n8.x4.trans.shared.b16 {%0,%1,%2,%3}, [%4];"
                 : "=r"(r0), "=r"(r1), "=r"(r2), "=r"(r3) : "r"(addr));
}
__device__ __forceinline__ void mma16816h(float* c, const uint32_t* a, const uint32_t* b) {
    asm volatile("mma.sync.aligned.m16n8k16.row.col.f32.f16.f16.f32 "
                 "{%0,%1,%2,%3}, {%4,%5,%6,%7}, {%8,%9}, {%0,%1,%2,%3};"
                 : "+f"(c[0]), "+f"(c[1]), "+f"(c[2]), "+f"(c[3])
                 : "r"(a[0]), "r"(a[1]), "r"(a[2]), "r"(a[3]),
                   "r"(b[0]), "r"(b[1]));
}
__device__ __forceinline__ uint32_t packh2(float x, float y) {
    __half2 h = __halves2half2(__float2half(x), __float2half(y));
    return *(uint32_t*)&h;
}

// ---------------------------------------------------------------------------
// truncate: fp32 -> fp16, same layout.
// ---------------------------------------------------------------------------
__global__ void trunc_kernel(const float* __restrict__ in,
                             __half* __restrict__ h, int n4)
{
    int i = blockIdx.x * blockDim.x + threadIdx.x;
    if (i >= n4) return;
    float4 v = ((const float4*)in)[i];
    ((__half2*)h)[2 * i]     = __half2(__float2half(v.x), __float2half(v.y));
    ((__half2*)h)[2 * i + 1] = __half2(__float2half(v.z), __float2half(v.w));
}

// ---------------------------------------------------------------------------
// transpose + truncate: W[K,N] fp32 -> T_h [N,K] fp16
// ---------------------------------------------------------------------------
__global__ void tsplit_kernel(const float* __restrict__ W,
                              __half* __restrict__ Th, int K, int N)
{
    __shared__ float t[32][33];
    int n0 = blockIdx.x * 32, k0 = blockIdx.y * 32;
    int tx = threadIdx.x, ty = threadIdx.y;  // 32 x 8
#pragma unroll
    for (int i = 0; i < 4; i++)
        t[ty + i * 8][tx] = W[(long)(k0 + ty + i * 8) * N + n0 + tx];
    __syncthreads();
#pragma unroll
    for (int i = 0; i < 4; i++) {
        float v = t[tx][ty + i * 8];
        Th[(long)(n0 + ty + i * 8) * K + k0 + tx] = __float2half(v);
    }
}

// ---------------------------------------------------------------------------
// GEMM mainloop: single-product fp16, 128x128x64 CTA tile, 256 threads,
// 8 warps (2Mx4N), 2-stage cp.async, ONE sync per stage. (R13 shape, best.)
// ---------------------------------------------------------------------------
#define ROWB    144
#define TILE_B  (128 * ROWB)
#define STAGE_B (2 * TILE_B)
#define GEMM_SMEM_DYN (2 * STAGE_B)

#define GEMM_MAINLOOP(Ah, Bh, K)                                                \
    extern __shared__ __align__(128) char smem[];                               \
    const uint32_t sbase = smem_to_u32(smem);                                   \
    const int tid  = threadIdx.x;                                               \
    const int lane = tid & 31;                                                  \
    const int wid  = tid >> 5;                                                  \
    const int wm   = wid & 1;                                                   \
    const int wn   = wid >> 1;                                                  \
    const int bm   = blockIdx.y * 128;                                          \
    const int bn   = blockIdx.x * 128;                                          \
    float acc[4][4][4];                                                         \
    _Pragma("unroll")                                                           \
    for (int mi = 0; mi < 4; mi++)                                              \
        _Pragma("unroll")                                                       \
        for (int ni = 0; ni < 4; ni++)                                          \
            _Pragma("unroll")                                                   \
            for (int r = 0; r < 4; r++) acc[mi][ni][r] = 0.f;                   \
    const __half* gA = Ah + (long)bm * (K);                                     \
    const __half* gB = Bh + (long)bn * (K);                                     \
    const int NS = (K) / 64;                                                    \
    auto load_stage = [&](int s) {                                              \
        const int k0 = s * 64;                                                  \
        const uint32_t buf = sbase + (s & 1) * STAGE_B;                         \
        _Pragma("unroll")                                                       \
        for (int p = 0; p < 4; p++) {                                           \
            int lin = tid + p * 256;                                            \
            int r = lin >> 3, c = lin & 7;                                      \
            cp_async16(buf + r * ROWB + c * 16,                                 \
                       gA + (long)r * (K) + k0 + c * 8);                        \
            cp_async16(buf + TILE_B + r * ROWB + c * 16,                        \
                       gB + (long)r * (K) + k0 + c * 8);                        \
        }                                                                       \
    };                                                                          \
    load_stage(0);                                                              \
    CP_COMMIT();                                                                \
    const int arow  = wm * 64 + (lane & 15);                                    \
    const int asel  = (lane >> 4) << 3;                                         \
    const int brow  = wn * 32 + (lane & 7) + ((lane >> 4) << 3);                \
    const int bsel  = ((lane >> 3) & 1) << 3;                                   \
    for (int s = 0; s < NS; s++) {                                              \
        CP_WAIT(0);                                                             \
        __syncthreads();                                                        \
        if (s + 1 < NS) {                                                       \
            load_stage(s + 1);                                                  \
            CP_COMMIT();                                                        \
        }                                                                       \
        const uint32_t buf = sbase + (s & 1) * STAGE_B;                         \
        _Pragma("unroll")                                                       \
        for (int ks = 0; ks < 4; ks++) {                                        \
            uint32_t a[4][4];                                                   \
            uint32_t b[4][2];                                                   \
            const int acol = ks * 16 + asel;                                    \
            const int bcol = ks * 16 + bsel;                                    \
            _Pragma("unroll")                                                   \
            for (int nj = 0; nj < 2; nj++)                                      \
                ldsm_x4(b[nj * 2][0], b[nj * 2][1],                             \
                        b[nj * 2 + 1][0], b[nj * 2 + 1][1],                     \
                        buf + TILE_B + (brow + nj * 16) * ROWB + bcol * 2);     \
            _Pragma("unroll")                                                   \
            for (int mi = 0; mi < 4; mi++)                                      \
                ldsm_x4(a[mi][0], a[mi][1], a[mi][2], a[mi][3],                 \
                        buf + (arow + mi * 16) * ROWB + acol * 2);              \
            _Pragma("unroll")                                                   \
            for (int mi = 0; mi < 4; mi++)                                      \
                _Pragma("unroll")                                               \
                for (int ni = 0; ni < 4; ni++)                                  \
                    mma16816h(acc[mi][ni], a[mi], b[ni]);                       \
        }                                                                       \
    }

// ---------------------------------------------------------------------------
// Projection GEMM: fp32 out + bias (final output)
// ---------------------------------------------------------------------------
__global__ void __launch_bounds__(256, 2) gemm_proj(
    const __half* __restrict__ Ah, const __half* __restrict__ Bh,
    const float* __restrict__ bias, float* __restrict__ C, int N, int K)
{
    GEMM_MAINLOOP(Ah, Bh, K)

    const int g  = lane >> 2;
    const int t4 = lane & 3;
#pragma unroll
    for (int mi = 0; mi < 4; mi++) {
#pragma unroll
        for (int ni = 0; ni < 4; ni++) {
            const int col = bn + wn * 32 + ni * 8 + t4 * 2;
            const long r0 = bm + wm * 64 + mi * 16 + g;
            float2 bb = *(const float2*)&bias[col];
            float2 o0 = { acc[mi][ni][0] + bb.x, acc[mi][ni][1] + bb.y };
            float2 o1 = { acc[mi][ni][2] + bb.x, acc[mi][ni][3] + bb.y };
            *(float2*)&C[r0 * N + col] = o0;
            *(float2*)&C[(r0 + 8) * N + col] = o1;
        }
    }
}

// ---------------------------------------------------------------------------
// QKV GEMM: epilogue writes Q(scaled)/K/V fp16 trunc directly to [b,h,s,d].
// ---------------------------------------------------------------------------
__global__ void __launch_bounds__(256, 2) gemm_qkv(
    const __half* __restrict__ Ah, const __half* __restrict__ Bh,
    const float* __restrict__ bias,
    __half* __restrict__ Qh, __half* __restrict__ Kh, __half* __restrict__ Vh,
    int K)
{
    GEMM_MAINLOOP(Ah, Bh, K)

    const int g  = lane >> 2;
    const int t4 = lane & 3;
    const int region = bn >> 10;            // 0=Q 1=K 2=V
    __half* Dh;
    float scale = 1.f;
    if (region == 0) { Dh = Qh; scale = 0.125f; }
    else if (region == 1) { Dh = Kh; }
    else { Dh = Vh; }

#pragma unroll
    for (int mi = 0; mi < 4; mi++) {
#pragma unroll
        for (int ni = 0; ni < 4; ni++) {
            const int colg = bn + wn * 32 + ni * 8 + t4 * 2;
            const int c    = colg & 1023;
            const int h    = c >> 6, d = c & 63;
            const long r0  = bm + wm * 64 + mi * 16 + g;       // = b*S + s
            const int b    = (int)(r0 >> 10);
            const int s    = (int)(r0 & 1023);
            float2 bb = *(const float2*)&bias[colg];
            long o = (((long)b * H_ + h) * S_ + s) * D_ + d;
            *(__half2*)&Dh[o] =
                __half2(__float2half((acc[mi][ni][0] + bb.x) * scale),
                        __float2half((acc[mi][ni][1] + bb.y) * scale));
            *(__half2*)&Dh[o + 8 * D_] =
                __half2(__float2half((acc[mi][ni][2] + bb.x) * scale),
                        __float2half((acc[mi][ni][3] + bb.y) * scale));
        }
    }
}

// ---------------------------------------------------------------------------
// Causal flash-attention, split-softmax + double-buffered K/V, ONE sync/tile.
// 64q x 64k tiles; 8 warps: wm {0..3} (16 q-rows), wn {0,1} (32 k-cols each).
// Each wn half keeps private (m, l, O); combined once in the epilogue.
// ---------------------------------------------------------------------------
#define ATS 72                                   // halfs per smem row (144 B)
#define Q_H 0
#define KV0 (64 * ATS)                           // stage s: K at KV0+s*KVS, V at +64*ATS
#define KVS (128 * ATS)
#define OS_OFF   ((64 + 2 * 128) * ATS * 2)      // bytes; fp32 Os[64][68]
#define OS_STR   68
#define MB_OFF   (OS_OFF + 64 * OS_STR * 4)      // fp32 m1buf[64], l1buf[64]
#define ATTN2_SMEM (MB_OFF + 2 * 64 * 4)

__global__ void __launch_bounds__(256, 2) attn_mma(
    const __half* __restrict__ Qh, const __half* __restrict__ Kh,
    const __half* __restrict__ Vh, __half* __restrict__ Oh)
{
    extern __shared__ __align__(128) char asmem[];
    const uint32_t sb = smem_to_u32(asmem);
    float* Os   = (float*)(asmem + OS_OFF);
    float* m1b  = (float*)(asmem + MB_OFF);
    float* l1b  = m1b + 64;

    const int tid  = threadIdx.x;
    const int lane = tid & 31;
    const int wid  = tid >> 5;
    const int wm   = wid & 3;
    const int wn   = wid >> 2;
    const int qt   = blockIdx.x;
    const int h    = blockIdx.y;
    const int b    = blockIdx.z;
    const int q0   = qt * 64;
    const long bh  = (long)b * H_ + h;

    const int g    = lane >> 2;
    const int t4   = lane & 3;
    const int row0 = wm * 16 + g;
    const int row1 = row0 + 8;

    // ---- Q tile + KV stage 0
    {
        const __half* qs = Qh + (bh * S_ + q0) * D_;
#pragma unroll
        for (int j = 0; j < 2; j++) {
            int lin = tid + j * 256;
            int r = lin >> 3, c = lin & 7;
            cp_async16(sb + (Q_H + r * ATS) * 2 + c * 16, qs + (long)r * D_ + c * 8);
        }
    }
    auto load_kv = [&](int kt) {
        const uint32_t base = KV0 + (kt & 1) * KVS;
        const __half* ks = Kh + (bh * S_ + kt * 64) * D_;
        const __half* vs = Vh + (bh * S_ + kt * 64) * D_;
#pragma unroll
        for (int j = 0; j < 2; j++) {
            int lin = tid + j * 256;
            int r = lin >> 3, c = lin & 7;
            cp_async16(sb + (base + r * ATS) * 2 + c * 16, ks + (long)r * D_ + c * 8);
            cp_async16(sb + (base + (64 + r) * ATS) * 2 + c * 16, vs + (long)r * D_ + c * 8);
        }
    };
    load_kv(0);
    CP_COMMIT();

    float m2[2] = { -1e30f, -1e30f }, l2[2] = { 0.f, 0.f };
    float oacc[8][4];
#pragma unroll
    for (int nt = 0; nt < 8; nt++)
#pragma unroll
        for (int r = 0; r < 4; r++) oacc[nt][r] = 0.f;

    const int arow = wm * 16 + (lane & 15);
    const int asel = (lane >> 4) << 3;
    const int brow = wn * 32 + (lane & 7) + ((lane >> 4) << 3);
    const int bsel = ((lane >> 3) & 1) << 3;
    const int vrow = ((lane >> 3) & 1) * 8 + (lane & 7);
    const int vcol = (lane >> 4) << 3;

    for (int kt = 0; kt <= qt; kt++) {
        CP_WAIT(0);
        __syncthreads();     // current KV visible; prev readers done before next load
        if (kt + 1 <= qt) {
            load_kv(kt + 1);
            CP_COMMIT();
        }
        const uint32_t kbuf = KV0 + (kt & 1) * KVS;
        const uint32_t vbuf = kbuf + 64 * ATS;

        // ---- S = Q @ K^T
        float s[4][4];
#pragma unroll
        for (int ni = 0; ni < 4; ni++)
#pragma unroll
            for (int r = 0; r < 4; r++) s[ni][r] = 0.f;

#pragma unroll
        for (int ks = 0; ks < 4; ks++) {
            const int acol = ks * 16 + asel;
            const int bcol = ks * 16 + bsel;
            uint32_t a[4], bq[4][2];
            ldsm_x4(a[0], a[1], a[2], a[3], sb + (Q_H + arow * ATS + acol) * 2);
#pragma unroll
            for (int nj = 0; nj < 2; nj++)
                ldsm_x4(bq[nj * 2][0], bq[nj * 2][1], bq[nj * 2 + 1][0], bq[nj * 2 + 1][1],
                        sb + (kbuf + (brow + nj * 16) * ATS + bcol) * 2);
#pragma unroll
            for (int ni = 0; ni < 4; ni++)
                mma16816h(s[ni], a, bq[ni]);
        }

        // ---- causal mask (diagonal tile)
        if (kt == qt) {
#pragma unroll
            for (int ni = 0; ni < 4; ni++) {
                const int col = wn * 32 + ni * 8 + t4 * 2;
                if (col > row0)     s[ni][0] = -1e9f;
                if (col + 1 > row0) s[ni][1] = -1e9f;
                if (col > row1)     s[ni][2] = -1e9f;
                if (col + 1 > row1) s[ni][3] = -1e9f;
            }
        }

        // ---- local (per-wn-half) online softmax: quad shfl only, no barriers
        float mx0 = -1e30f, mx1 = -1e30f;
#pragma unroll
        for (int ni = 0; ni < 4; ni++) {
            mx0 = fmaxf(mx0, fmaxf(s[ni][0], s[ni][1]));
            mx1 = fmaxf(mx1, fmaxf(s[ni][2], s[ni][3]));
        }
        mx0 = fmaxf(mx0, __shfl_xor_sync(0xffffffffu, mx0, 1));
        mx0 = fmaxf(mx0, __shfl_xor_sync(0xffffffffu, mx0, 2));
        mx1 = fmaxf(mx1, __shfl_xor_sync(0xffffffffu, mx1, 1));
        mx1 = fmaxf(mx1, __shfl_xor_sync(0xffffffffu, mx1, 2));
        const float mn0 = fmaxf(m2[0], mx0), mn1 = fmaxf(m2[1], mx1);
        const float alpha0 = __expf(m2[0] - mn0), alpha1 = __expf(m2[1] - mn1);
        m2[0] = mn0; m2[1] = mn1;

        float rs0 = 0.f, rs1 = 0.f;
#pragma unroll
        for (int ni = 0; ni < 4; ni++) {
            s[ni][0] = __expf(s[ni][0] - mn0);
            s[ni][1] = __expf(s[ni][1] - mn0);
            s[ni][2] = __expf(s[ni][2] - mn1);
            s[ni][3] = __expf(s[ni][3] - mn1);
            rs0 += s[ni][0] + s[ni][1];
            rs1 += s[ni][2] + s[ni][3];
        }
        rs0 += __shfl_xor_sync(0xffffffffu, rs0, 1);
        rs0 += __shfl_xor_sync(0xffffffffu, rs0, 2);
        rs1 += __shfl_xor_sync(0xffffffffu, rs1, 1);
        rs1 += __shfl_xor_sync(0xffffffffu, rs1, 2);
        l2[0] = l2[0] * alpha0 + rs0;
        l2[1] = l2[1] * alpha1 + rs1;

        // ---- P as PV A-fragments straight from C-regs
        uint32_t pa[2][4];
#pragma unroll
        for (int j = 0; j < 2; j++) {
            pa[j][0] = packh2(s[2 * j][0],     s[2 * j][1]);
            pa[j][1] = packh2(s[2 * j][2],     s[2 * j][3]);
            pa[j][2] = packh2(s[2 * j + 1][0], s[2 * j + 1][1]);
            pa[j][3] = packh2(s[2 * j + 1][2], s[2 * j + 1][3]);
        }

        // ---- O = O*alpha + P @ V (this wn's 32 k-rows, all 64 d)
#pragma unroll
        for (int nt = 0; nt < 8; nt++) {
            oacc[nt][0] *= alpha0; oacc[nt][1] *= alpha0;
            oacc[nt][2] *= alpha1; oacc[nt][3] *= alpha1;
        }
#pragma unroll
        for (int j = 0; j < 2; j++) {
            const int kb = wn * 32 + j * 16;
            uint32_t bv[8][2];
#pragma unroll
            for (int nj = 0; nj < 4; nj++)
                ldsm_x4t(bv[nj * 2][0], bv[nj * 2][1], bv[nj * 2 + 1][0], bv[nj * 2 + 1][1],
                         sb + (vbuf + (kb + vrow) * ATS + vcol + nj * 16) * 2);
#pragma unroll
            for (int nt = 0; nt < 8; nt++)
                mma16816h(oacc[nt], pa[j], bv[nt]);
        }
    }

    // ---- epilogue: combine the two wn halves with split-softmax merge
    if (wn == 1) {
        if (t4 == 0) {
            m1b[row0] = m2[0]; l1b[row0] = l2[0];
            m1b[row1] = m2[1]; l1b[row1] = l2[1];
        }
#pragma unroll
        for (int nt = 0; nt < 8; nt++) {
            const int c = nt * 8 + t4 * 2;
            Os[row0 * OS_STR + c]     = oacc[nt][0];
            Os[row0 * OS_STR + c + 1] = oacc[nt][1];
            Os[row1 * OS_STR + c]     = oacc[nt][2];
            Os[row1 * OS_STR + c + 1] = oacc[nt][3];
        }
    }
    __syncthreads();
    if (wn == 0) {
        const float mo0 = m1b[row0], mo1 = m1b[row1];
        const float M0 = fmaxf(m2[0], mo0), M1 = fmaxf(m2[1], mo1);
        const float f00 = __expf(m2[0] - M0), f01 = __expf(mo0 - M0);
        const float f10 = __expf(m2[1] - M1), f11 = __expf(mo1 - M1);
        const float inv0 = 1.f / (l2[0] * f00 + l1b[row0] * f01);
        const float inv1 = 1.f / (l2[1] * f10 + l1b[row1] * f11);
        const long r0 = (long)b * S_ + q0 + row0;
#pragma unroll
        for (int nt = 0; nt < 8; nt++) {
            const int c = nt * 8 + t4 * 2;
            const int col = h * D_ + c;
            float f0 = (oacc[nt][0] * f00 + Os[row0 * OS_STR + c]     * f01) * inv0;
            float f1 = (oacc[nt][1] * f00 + Os[row0 * OS_STR + c + 1] * f01) * inv0;
            float f2 = (oacc[nt][2] * f10 + Os[row1 * OS_STR + c]     * f11) * inv1;
            float f3 = (oacc[nt][3] * f10 + Os[row1 * OS_STR + c + 1] * f11) * inv1;
            *(__half2*)&Oh[r0 * NX_ + col] =
                __half2(__float2half(f0), __float2half(f1));
            *(__half2*)&Oh[(r0 + 8) * NX_ + col] =
                __half2(__float2half(f2), __float2half(f3));
        }
    }
}

// ---------------------------------------------------------------------------
extern "C" void kernel_launch(void* const* d_in, const int* in_sizes, int n_in,
                              void* d_out, int out_size)
{
    const float* x      = (const float*)d_in[0];
    const float* w_attn = (const float*)d_in[1];
    const float* b_attn = (const float*)d_in[2];
    const float* w_proj = (const float*)d_in[3];
    const float* b_proj = (const float*)d_in[4];
    float* out = (float*)d_out;

    __half *xh, *ah, *wqh, *wph, *qh, *kh, *vh;
    cudaGetSymbolAddress((void**)&xh, g_xh);
    cudaGetSymbolAddress((void**)&ah, g_ah);
    cudaGetSymbolAddress((void**)&wqh, g_wqkv_h);
    cudaGetSymbolAddress((void**)&wph, g_wproj_h);
    cudaGetSymbolAddress((void**)&qh, g_qh);
    cudaGetSymbolAddress((void**)&kh, g_kh);
    cudaGetSymbolAddress((void**)&vh, g_vh);

    cudaFuncSetAttribute(attn_mma,
                         cudaFuncAttributeMaxDynamicSharedMemorySize, ATTN2_SMEM);
    cudaFuncSetAttribute(gemm_qkv,
                         cudaFuncAttributeMaxDynamicSharedMemorySize, GEMM_SMEM_DYN);
    cudaFuncSetAttribute(gemm_proj,
                         cudaFuncAttributeMaxDynamicSharedMemorySize, GEMM_SMEM_DYN);

    const int M = B_ * S_;  // 8192

    // truncate x to fp16
    {
        int n4 = M * NX_ / 4;
        trunc_kernel<<<(n4 + 255) / 256, 256>>>(x, xh, n4);
    }
    // transpose+truncate weights (fp16)
    tsplit_kernel<<<dim3(3 * NX_ / 32, NX_ / 32), dim3(32, 8)>>>(w_attn, wqh, NX_, 3 * NX_);
    tsplit_kernel<<<dim3(NX_ / 32, NX_ / 32), dim3(32, 8)>>>(w_proj, wph, NX_, NX_);

    // QKV GEMM (single-product fp16) with fused fp16 epilogue
    gemm_qkv<<<dim3(3 * NX_ / 128, M / 128), 256, GEMM_SMEM_DYN>>>(
        xh, wqh, b_attn, qh, kh, vh, NX_);

    // attention (split-softmax, double-buffered K/V) -> fp16 trunc
    attn_mma<<<dim3(S_ / 64, H_, B_), 256, ATTN2_SMEM>>>(qh, kh, vh, ah);

    // projection GEMM (single-product fp16) -> final fp32 output
    gemm_proj<<<dim3(NX_ / 128, M / 128), 256, GEMM_SMEM_DYN>>>(
        ah, wph, b_proj, out, NX_, NX_);
}

// round 15
// speedup vs baseline: 2.8151x; 1.0277x over previous
#include <cuda_runtime.h>
#include <cuda_bf16.h>
#include <cuda_fp16.h>
#include <cstdint>

#define B_  8
#define S_  1024
#define NX_ 1024
#define H_  16
#define D_  64

// ---------------- scratch (__device__ globals; no allocation) ----------------
__device__ __half g_xh[B_ * S_ * NX_];               // x, fp16 trunc
__device__ __half g_ah[B_ * S_ * NX_];               // attention out, fp16 trunc
__device__ __half g_wqkv_h[3 * NX_ * NX_];           // [N=3072, K=1024] fp16 trunc
__device__ __half g_wproj_h[NX_ * NX_];              // [N=1024, K=1024]
__device__ __half g_qh[B_ * H_ * S_ * D_];           // [b,h,s,d], pre-scaled 0.125
__device__ __half g_kh[B_ * H_ * S_ * D_];
__device__ __half g_vh[B_ * H_ * S_ * D_];

// ---------------- PTX helpers ----------------
__device__ __forceinline__ uint32_t smem_to_u32(const void* p) {
    uint32_t a;
    asm("{ .reg .u64 t; cvta.to.shared.u64 t, %1; cvt.u32.u64 %0, t; }"
        : "=r"(a) : "l"(p));
    return a;
}
__device__ __forceinline__ void cp_async16(uint32_t dst, const void* src) {
    asm volatile("cp.async.cg.shared.global [%0], [%1], 16;"
                 :: "r"(dst), "l"(src) : "memory");
}
#define CP_COMMIT() asm volatile("cp.async.commit_group;" ::: "memory")
#define CP_WAIT(n)  asm volatile("cp.async.wait_group %0;" :: "n"(n) : "memory")

__device__ __forceinline__ void ldsm_x4(uint32_t& r0, uint32_t& r1,
                                        uint32_t& r2, uint32_t& r3, uint32_t addr) {
    asm volatile("ldmatrix.sync.aligned.m8n8.x4.shared.b16 {%0,%1,%2,%3}, [%4];"
                 : "=r"(r0), "=r"(r1), "=r"(r2), "=r"(r3) : "r"(addr));
}
__device__ __forceinline__ void ldsm_x4t(uint32_t& r0, uint32_t& r1,
                                         uint32_t& r2, uint32_t& r3, uint32_t addr) {
    asm volatile("ldmatrix.sync.aligned.m8n8.x4.trans.shared.b16 {%0,%1,%2,%3}, [%4];"
                 : "=r"(r0), "=r"(r1), "=r"(r2), "=r"(r3) : "r"(addr));
}
__device__ __forceinline__ void mma16816h(float* c, const uint32_t* a, const uint32_t* b) {
    asm volatile("mma.sync.aligned.m16n8k16.row.col.f32.f16.f16.f32 "
                 "{%0,%1,%2,%3}, {%4,%5,%6,%7}, {%8,%9}, {%0,%1,%2,%3};"
                 : "+f"(c[0]), "+f"(c[1]), "+f"(c[2]), "+f"(c[3])
                 : "r"(a[0]), "r"(a[1]), "r"(a[2]), "r"(a[3]),
                   "r"(b[0]), "r"(b[1]));
}
__device__ __forceinline__ uint32_t packh2(float x, float y) {
    __half2 h = __halves2half2(__float2half(x), __float2half(y));
    return *(uint32_t*)&h;
}

// ---------------------------------------------------------------------------
// truncate: fp32 -> fp16, same layout.
// ---------------------------------------------------------------------------
__global__ void trunc_kernel(const float* __restrict__ in,
                             __half* __restrict__ h, int n4)
{
    int i = blockIdx.x * blockDim.x + threadIdx.x;
    if (i >= n4) return;
    float4 v = ((const float4*)in)[i];
    ((__half2*)h)[2 * i]     = __half2(__float2half(v.x), __float2half(v.y));
    ((__half2*)h)[2 * i + 1] = __half2(__float2half(v.z), __float2half(v.w));
}

// ---------------------------------------------------------------------------
// transpose + truncate: W[K,N] fp32 -> T_h [N,K] fp16
// ---------------------------------------------------------------------------
__global__ void tsplit_kernel(const float* __restrict__ W,
                              __half* __restrict__ Th, int K, int N)
{
    __shared__ float t[32][33];
    int n0 = blockIdx.x * 32, k0 = blockIdx.y * 32;
    int tx = threadIdx.x, ty = threadIdx.y;  // 32 x 8
#pragma unroll
    for (int i = 0; i < 4; i++)
        t[ty + i * 8][tx] = W[(long)(k0 + ty + i * 8) * N + n0 + tx];
    __syncthreads();
#pragma unroll
    for (int i = 0; i < 4; i++) {
        float v = t[tx][ty + i * 8];
        Th[(long)(n0 + ty + i * 8) * K + k0 + tx] = __float2half(v);
    }
}

// ---------------------------------------------------------------------------
// GEMM mainloop: single-product fp16, 128x128x64 CTA tile, 256 threads,
// 8 warps (2Mx4N), 2-stage cp.async, ONE sync per stage. (R13/R14 shape.)
// ---------------------------------------------------------------------------
#define ROWB    144
#define TILE_B  (128 * ROWB)
#define STAGE_B (2 * TILE_B)
#define GEMM_SMEM_DYN (2 * STAGE_B)

#define GEMM_MAINLOOP(Ah, Bh, K)                                                \
    extern __shared__ __align__(128) char smem[];                               \
    const uint32_t sbase = smem_to_u32(smem);                                   \
    const int tid  = threadIdx.x;                                               \
    const int lane = tid & 31;                                                  \
    const int wid  = tid >> 5;                                                  \
    const int wm   = wid & 1;                                                   \
    const int wn   = wid >> 1;                                                  \
    const int bm   = blockIdx.y * 128;                                          \
    const int bn   = blockIdx.x * 128;                                          \
    float acc[4][4][4];                                                         \
    _Pragma("unroll")                                                           \
    for (int mi = 0; mi < 4; mi++)                                              \
        _Pragma("unroll")                                                       \
        for (int ni = 0; ni < 4; ni++)                                          \
            _Pragma("unroll")                                                   \
            for (int r = 0; r < 4; r++) acc[mi][ni][r] = 0.f;                   \
    const __half* gA = Ah + (long)bm * (K);                                     \
    const __half* gB = Bh + (long)bn * (K);                                     \
    const int NS = (K) / 64;                                                    \
    auto load_stage = [&](int s) {                                              \
        const int k0 = s * 64;                                                  \
        const uint32_t buf = sbase + (s & 1) * STAGE_B;                         \
        _Pragma("unroll")                                                       \
        for (int p = 0; p < 4; p++) {                                           \
            int lin = tid + p * 256;                                            \
            int r = lin >> 3, c = lin & 7;                                      \
            cp_async16(buf + r * ROWB + c * 16,                                 \
                       gA + (long)r * (K) + k0 + c * 8);                        \
            cp_async16(buf + TILE_B + r * ROWB + c * 16,                        \
                       gB + (long)r * (K) + k0 + c * 8);                        \
        }                                                                       \
    };                                                                          \
    load_stage(0);                                                              \
    CP_COMMIT();                                                                \
    const int arow  = wm * 64 + (lane & 15);                                    \
    const int asel  = (lane >> 4) << 3;                                         \
    const int brow  = wn * 32 + (lane & 7) + ((lane >> 4) << 3);                \
    const int bsel  = ((lane >> 3) & 1) << 3;                                   \
    for (int s = 0; s < NS; s++) {                                              \
        CP_WAIT(0);                                                             \
        __syncthreads();                                                        \
        if (s + 1 < NS) {                                                       \
            load_stage(s + 1);                                                  \
            CP_COMMIT();                                                        \
        }                                                                       \
        const uint32_t buf = sbase + (s & 1) * STAGE_B;                         \
        _Pragma("unroll")                                                       \
        for (int ks = 0; ks < 4; ks++) {                                        \
            uint32_t a[4][4];                                                   \
            uint32_t b[4][2];                                                   \
            const int acol = ks * 16 + asel;                                    \
            const int bcol = ks * 16 + bsel;                                    \
            _Pragma("unroll")                                                   \
            for (int nj = 0; nj < 2; nj++)                                      \
                ldsm_x4(b[nj * 2][0], b[nj * 2][1],                             \
                        b[nj * 2 + 1][0], b[nj * 2 + 1][1],                     \
                        buf + TILE_B + (brow + nj * 16) * ROWB + bcol * 2);     \
            _Pragma("unroll")                                                   \
            for (int mi = 0; mi < 4; mi++)                                      \
                ldsm_x4(a[mi][0], a[mi][1], a[mi][2], a[mi][3],                 \
                        buf + (arow + mi * 16) * ROWB + acol * 2);              \
            _Pragma("unroll")                                                   \
            for (int mi = 0; mi < 4; mi++)                                      \
                _Pragma("unroll")                                               \
                for (int ni = 0; ni < 4; ni++)                                  \
                    mma16816h(acc[mi][ni], a[mi], b[ni]);                       \
        }                                                                       \
    }

// ---------------------------------------------------------------------------
// Projection GEMM: fp32 out + bias (final output)
// ---------------------------------------------------------------------------
__global__ void __launch_bounds__(256, 2) gemm_proj(
    const __half* __restrict__ Ah, const __half* __restrict__ Bh,
    const float* __restrict__ bias, float* __restrict__ C, int N, int K)
{
    GEMM_MAINLOOP(Ah, Bh, K)

    const int g  = lane >> 2;
    const int t4 = lane & 3;
#pragma unroll
    for (int mi = 0; mi < 4; mi++) {
#pragma unroll
        for (int ni = 0; ni < 4; ni++) {
            const int col = bn + wn * 32 + ni * 8 + t4 * 2;
            const long r0 = bm + wm * 64 + mi * 16 + g;
            float2 bb = *(const float2*)&bias[col];
            float2 o0 = { acc[mi][ni][0] + bb.x, acc[mi][ni][1] + bb.y };
            float2 o1 = { acc[mi][ni][2] + bb.x, acc[mi][ni][3] + bb.y };
            *(float2*)&C[r0 * N + col] = o0;
            *(float2*)&C[(r0 + 8) * N + col] = o1;
        }
    }
}

// ---------------------------------------------------------------------------
// QKV GEMM: epilogue writes Q(scaled)/K/V fp16 trunc directly to [b,h,s,d].
// ---------------------------------------------------------------------------
__global__ void __launch_bounds__(256, 2) gemm_qkv(
    const __half* __restrict__ Ah, const __half* __restrict__ Bh,
    const float* __restrict__ bias,
    __half* __restrict__ Qh, __half* __restrict__ Kh, __half* __restrict__ Vh,
    int K)
{
    GEMM_MAINLOOP(Ah, Bh, K)

    const int g  = lane >> 2;
    const int t4 = lane & 3;
    const int region = bn >> 10;            // 0=Q 1=K 2=V
    __half* Dh;
    float scale = 1.f;
    if (region == 0) { Dh = Qh; scale = 0.125f; }
    else if (region == 1) { Dh = Kh; }
    else { Dh = Vh; }

#pragma unroll
    for (int mi = 0; mi < 4; mi++) {
#pragma unroll
        for (int ni = 0; ni < 4; ni++) {
            const int colg = bn + wn * 32 + ni * 8 + t4 * 2;
            const int c    = colg & 1023;
            const int h    = c >> 6, d = c & 63;
            const long r0  = bm + wm * 64 + mi * 16 + g;       // = b*S + s
            const int b    = (int)(r0 >> 10);
            const int s    = (int)(r0 & 1023);
            float2 bb = *(const float2*)&bias[colg];
            long o = (((long)b * H_ + h) * S_ + s) * D_ + d;
            *(__half2*)&Dh[o] =
                __half2(__float2half((acc[mi][ni][0] + bb.x) * scale),
                        __float2half((acc[mi][ni][1] + bb.y) * scale));
            *(__half2*)&Dh[o + 8 * D_] =
                __half2(__float2half((acc[mi][ni][2] + bb.x) * scale),
                        __float2half((acc[mi][ni][3] + bb.y) * scale));
        }
    }
}

// ---------------------------------------------------------------------------
// Causal flash-attention: 128-row Q tiles, 8 warps each owning 16 q-rows x
// ALL 64 k-cols -> fully warp-private softmax (quad shfl only), no cross-warp
// merge, no O smem. Double-buffered K/V, ONE sync per k-tile.
// ---------------------------------------------------------------------------
#define ATS 72                                   // halfs per smem row (144 B)
#define Q_H 0                                    // 128 rows
#define KV0 (128 * ATS)                          // stage s: K 64 rows, V 64 rows
#define KVS (128 * ATS)
#define ATTN2_SMEM ((128 + 2 * 128) * ATS * 2)   // 55296 B

__global__ void __launch_bounds__(256, 2) attn_mma(
    const __half* __restrict__ Qh, const __half* __restrict__ Kh,
    const __half* __restrict__ Vh, __half* __restrict__ Oh)
{
    extern __shared__ __align__(128) char asmem[];
    const uint32_t sb = smem_to_u32(asmem);

    const int tid  = threadIdx.x;
    const int lane = tid & 31;
    const int wid  = tid >> 5;               // 8 warps, 16 q-rows each
    const int qtile = 7 - (int)blockIdx.x;   // big work first (tail packing)
    const int h    = blockIdx.y;
    const int b    = blockIdx.z;
    const int q0   = qtile * 128;
    const long bh  = (long)b * H_ + h;

    const int g    = lane >> 2;
    const int t4   = lane & 3;
    const int row0 = q0 + wid * 16 + g;      // global q row
    const int row1 = row0 + 8;

    // ---- Q tile (128 rows x 64): 1024 chunks / 256 thr
    {
        const __half* qs = Qh + (bh * S_ + q0) * D_;
#pragma unroll
        for (int j = 0; j < 4; j++) {
            int lin = tid + j * 256;
            int r = lin >> 3, c = lin & 7;
            cp_async16(sb + (Q_H + r * ATS) * 2 + c * 16, qs + (long)r * D_ + c * 8);
        }
    }
    auto load_kv = [&](int kt) {
        const uint32_t base = KV0 + (kt & 1) * KVS;
        const __half* ks = Kh + (bh * S_ + kt * 64) * D_;
        const __half* vs = Vh + (bh * S_ + kt * 64) * D_;
#pragma unroll
        for (int j = 0; j < 2; j++) {
            int lin = tid + j * 256;
            int r = lin >> 3, c = lin & 7;
            cp_async16(sb + (base + r * ATS) * 2 + c * 16, ks + (long)r * D_ + c * 8);
            cp_async16(sb + (base + (64 + r) * ATS) * 2 + c * 16, vs + (long)r * D_ + c * 8);
        }
    };
    load_kv(0);
    CP_COMMIT();

    float m2[2] = { -1e30f, -1e30f }, l2[2] = { 0.f, 0.f };
    float oacc[8][4];
#pragma unroll
    for (int nt = 0; nt < 8; nt++)
#pragma unroll
        for (int r = 0; r < 4; r++) oacc[nt][r] = 0.f;

    const int arow = wid * 16 + (lane & 15);
    const int asel = (lane >> 4) << 3;
    const int brow = (lane & 7) + ((lane >> 4) << 3);
    const int bsel = ((lane >> 3) & 1) << 3;
    const int vrow = ((lane >> 3) & 1) * 8 + (lane & 7);
    const int vcol = (lane >> 4) << 3;

    const int NT = 2 * qtile + 2;            // k-tiles (64 each) to cover q0+127

    for (int kt = 0; kt < NT; kt++) {
        CP_WAIT(0);
        __syncthreads();
        if (kt + 1 < NT) {
            load_kv(kt + 1);
            CP_COMMIT();
        }
        const uint32_t kbuf = KV0 + (kt & 1) * KVS;
        const uint32_t vbuf = kbuf + 64 * ATS;

        // ---- S = Q @ K^T : warp covers 16 q-rows x 64 k-cols
        float s[8][4];
#pragma unroll
        for (int ni = 0; ni < 8; ni++)
#pragma unroll
            for (int r = 0; r < 4; r++) s[ni][r] = 0.f;

#pragma unroll
        for (int ks = 0; ks < 4; ks++) {
            const int acol = ks * 16 + asel;
            const int bcol = ks * 16 + bsel;
            uint32_t a[4], bq[8][2];
            ldsm_x4(a[0], a[1], a[2], a[3], sb + (Q_H + arow * ATS + acol) * 2);
#pragma unroll
            for (int nj = 0; nj < 4; nj++)
                ldsm_x4(bq[nj * 2][0], bq[nj * 2][1], bq[nj * 2 + 1][0], bq[nj * 2 + 1][1],
                        sb + (kbuf + (brow + nj * 16) * ATS + bcol) * 2);
#pragma unroll
            for (int ni = 0; ni < 8; ni++)
                mma16816h(s[ni], a, bq[ni]);
        }

        // ---- causal mask (only the last two k-tiles can touch the diagonal)
        if (kt >= 2 * qtile) {
            const int cb = kt * 64;
#pragma unroll
            for (int ni = 0; ni < 8; ni++) {
                const int col = cb + ni * 8 + t4 * 2;
                if (col > row0)     s[ni][0] = -1e9f;
                if (col + 1 > row0) s[ni][1] = -1e9f;
                if (col > row1)     s[ni][2] = -1e9f;
                if (col + 1 > row1) s[ni][3] = -1e9f;
            }
        }

        // ---- warp-private online softmax (quad shfl)
        float mx0 = -1e30f, mx1 = -1e30f;
#pragma unroll
        for (int ni = 0; ni < 8; ni++) {
            mx0 = fmaxf(mx0, fmaxf(s[ni][0], s[ni][1]));
            mx1 = fmaxf(mx1, fmaxf(s[ni][2], s[ni][3]));
        }
        mx0 = fmaxf(mx0, __shfl_xor_sync(0xffffffffu, mx0, 1));
        mx0 = fmaxf(mx0, __shfl_xor_sync(0xffffffffu, mx0, 2));
        mx1 = fmaxf(mx1, __shfl_xor_sync(0xffffffffu, mx1, 1));
        mx1 = fmaxf(mx1, __shfl_xor_sync(0xffffffffu, mx1, 2));
        const float mn0 = fmaxf(m2[0], mx0), mn1 = fmaxf(m2[1], mx1);
        const float alpha0 = __expf(m2[0] - mn0), alpha1 = __expf(m2[1] - mn1);
        m2[0] = mn0; m2[1] = mn1;

        float rs0 = 0.f, rs1 = 0.f;
#pragma unroll
        for (int ni = 0; ni < 8; ni++) {
            s[ni][0] = __expf(s[ni][0] - mn0);
            s[ni][1] = __expf(s[ni][1] - mn0);
            s[ni][2] = __expf(s[ni][2] - mn1);
            s[ni][3] = __expf(s[ni][3] - mn1);
            rs0 += s[ni][0] + s[ni][1];
            rs1 += s[ni][2] + s[ni][3];
        }
        rs0 += __shfl_xor_sync(0xffffffffu, rs0, 1);
        rs0 += __shfl_xor_sync(0xffffffffu, rs0, 2);
        rs1 += __shfl_xor_sync(0xffffffffu, rs1, 1);
        rs1 += __shfl_xor_sync(0xffffffffu, rs1, 2);
        l2[0] = l2[0] * alpha0 + rs0;
        l2[1] = l2[1] * alpha1 + rs1;

        // ---- O = O*alpha + P @ V (all 64 k, all 64 d)
#pragma unroll
        for (int nt = 0; nt < 8; nt++) {
            oacc[nt][0] *= alpha0; oacc[nt][1] *= alpha0;
            oacc[nt][2] *= alpha1; oacc[nt][3] *= alpha1;
        }
#pragma unroll
        for (int j = 0; j < 4; j++) {
            uint32_t pa[4];
            pa[0] = packh2(s[2 * j][0],     s[2 * j][1]);
            pa[1] = packh2(s[2 * j][2],     s[2 * j][3]);
            pa[2] = packh2(s[2 * j + 1][0], s[2 * j + 1][1]);
            pa[3] = packh2(s[2 * j + 1][2], s[2 * j + 1][3]);
            const int kb = j * 16;
            uint32_t bv[8][2];
#pragma unroll
            for (int nj = 0; nj < 4; nj++)
                ldsm_x4t(bv[nj * 2][0], bv[nj * 2][1], bv[nj * 2 + 1][0], bv[nj * 2 + 1][1],
                         sb + (vbuf + (kb + vrow) * ATS + vcol + nj * 16) * 2);
#pragma unroll
            for (int nt = 0; nt < 8; nt++)
                mma16816h(oacc[nt], pa, bv[nt]);
        }
    }

    // ---- epilogue: warp-private normalize + write (no merge needed)
    const float inv0 = 1.f / l2[0], inv1 = 1.f / l2[1];
    const long r0 = (long)b * S_ + row0;
#pragma unroll
    for (int nt = 0; nt < 8; nt++) {
        const int col = h * D_ + nt * 8 + t4 * 2;
        *(__half2*)&Oh[r0 * NX_ + col] =
            __half2(__float2half(oacc[nt][0] * inv0), __float2half(oacc[nt][1] * inv0));
        *(__half2*)&Oh[(r0 + 8) * NX_ + col] =
            __half2(__float2half(oacc[nt][2] * inv1), __float2half(oacc[nt][3] * inv1));
    }
}

// ---------------------------------------------------------------------------
extern "C" void kernel_launch(void* const* d_in, const int* in_sizes, int n_in,
                              void* d_out, int out_size)
{
    const float* x      = (const float*)d_in[0];
    const float* w_attn = (const float*)d_in[1];
    const float* b_attn = (const float*)d_in[2];
    const float* w_proj = (const float*)d_in[3];
    const float* b_proj = (const float*)d_in[4];
    float* out = (float*)d_out;

    __half *xh, *ah, *wqh, *wph, *qh, *kh, *vh;
    cudaGetSymbolAddress((void**)&xh, g_xh);
    cudaGetSymbolAddress((void**)&ah, g_ah);
    cudaGetSymbolAddress((void**)&wqh, g_wqkv_h);
    cudaGetSymbolAddress((void**)&wph, g_wproj_h);
    cudaGetSymbolAddress((void**)&qh, g_qh);
    cudaGetSymbolAddress((void**)&kh, g_kh);
    cudaGetSymbolAddress((void**)&vh, g_vh);

    cudaFuncSetAttribute(attn_mma,
                         cudaFuncAttributeMaxDynamicSharedMemorySize, ATTN2_SMEM);
    cudaFuncSetAttribute(gemm_qkv,
                         cudaFuncAttributeMaxDynamicSharedMemorySize, GEMM_SMEM_DYN);
    cudaFuncSetAttribute(gemm_proj,
                         cudaFuncAttributeMaxDynamicSharedMemorySize, GEMM_SMEM_DYN);

    const int M = B_ * S_;  // 8192

    // truncate x to fp16
    {
        int n4 = M * NX_ / 4;
        trunc_kernel<<<(n4 + 255) / 256, 256>>>(x, xh, n4);
    }
    // transpose+truncate weights (fp16)
    tsplit_kernel<<<dim3(3 * NX_ / 32, NX_ / 32), dim3(32, 8)>>>(w_attn, wqh, NX_, 3 * NX_);
    tsplit_kernel<<<dim3(NX_ / 32, NX_ / 32), dim3(32, 8)>>>(w_proj, wph, NX_, NX_);

    // QKV GEMM (single-product fp16) with fused fp16 epilogue
    gemm_qkv<<<dim3(3 * NX_ / 128, M / 128), 256, GEMM_SMEM_DYN>>>(
        xh, wqh, b_attn, qh, kh, vh, NX_);

    // attention (128-row Q tiles, warp-private softmax) -> fp16 trunc
    attn_mma<<<dim3(S_ / 128, H_, B_), 256, ATTN2_SMEM>>>(qh, kh, vh, ah);

    // projection GEMM (single-product fp16) -> final fp32 output
    gemm_proj<<<dim3(NX_ / 128, M / 128), 256, GEMM_SMEM_DYN>>>(
        ah, wph, b_proj, out, NX_, NX_);
}